// round 15
// baseline (speedup 1.0000x reference)
#include <cuda_runtime.h>
#include <cuda_bf16.h>
#include <stdint.h>
#include <math.h>

typedef __nv_bfloat16 bf16;
typedef unsigned int u32;

#define C_DIM 512
#define M_TOT 65536
#define INV_M (1.0f / 65536.0f)
#define EPS_V 1e-5f

#define ROWB 144                 // 64 bf16 = 128B data + 16B pad
// 128x256 tiling (gram_big + gemm_out): BK=64, 8 warps (2x4), warp 64x64
#define TILE_A (128 * ROWB)      // 18432
#define TILE_BO (256 * ROWB)     // 36864
#define OFF_B (2 * TILE_A)       // 36864
#define STAGE_O (2 * TILE_A + 2 * TILE_BO)  // 110592
#define GSMEM_O (2 * STAGE_O)    // 221184

// NS tiling: CTA 64x64, 256 threads, 2 K-groups of 4 warps
#define TILE64 (64 * ROWB)       // 9216
#define STAGE64G (4 * TILE64)    // 36864
#define NS_SMEM (4 * STAGE64G)   // 147456

// gram tri tiling: 4 wide (128x256) + 2 narrow (128x128) tiles
__constant__ int c_tr[6] = {0, 0, 128, 256, 128, 384};
__constant__ int c_tc[6] = {0, 256, 256, 256, 128, 384};

// ---------------- scratch ----------------
__device__ float g_mean[C_DIM];     // channel SUMS (x INV_M at use)
__device__ float g_bias[C_DIM];
__device__ float g_Gram[C_DIM * C_DIM];
__device__ float g_rTr;
__device__ float g_tr;
__device__ bf16 g_Xh[33554432];   // RAW X, [c][m]
__device__ bf16 g_Xl[33554432];
__device__ bf16 g_Xth[33554432];  // RAW X, [m][c]
__device__ bf16 g_Xtl[33554432];
__device__ bf16 g_Sh[C_DIM * C_DIM], g_Sl[C_DIM * C_DIM];
__device__ bf16 g_PAh[C_DIM * C_DIM], g_PAl[C_DIM * C_DIM];
__device__ bf16 g_PBh[C_DIM * C_DIM], g_PBl[C_DIM * C_DIM];
__device__ bf16 g_T1h[C_DIM * C_DIM], g_T1l[C_DIM * C_DIM];
__device__ bf16 g_Uh[C_DIM * C_DIM], g_Ul[C_DIM * C_DIM];
__device__ bf16 g_Wh[C_DIM * C_DIM], g_Wl[C_DIM * C_DIM];
__device__ float g_PfA[C_DIM * C_DIM], g_PfB[C_DIM * C_DIM];

// ---------------- helpers ----------------
__device__ __forceinline__ u32 s2u(const void* p) {
    u32 a;
    asm("{ .reg .u64 t; cvta.to.shared.u64 t, %1; cvt.u32.u64 %0, t; }" : "=r"(a) : "l"(p));
    return a;
}
__device__ __forceinline__ void cpasync16(u32 dst, const void* src) {
    asm volatile("cp.async.cg.shared.global [%0], [%1], 16;" :: "r"(dst), "l"(src));
}
__device__ __forceinline__ void ldm4(u32* r, u32 addr) {
    asm volatile("ldmatrix.sync.aligned.m8n8.x4.shared.b16 {%0,%1,%2,%3}, [%4];"
                 : "=r"(r[0]), "=r"(r[1]), "=r"(r[2]), "=r"(r[3]) : "r"(addr));
}
__device__ __forceinline__ void mma16816(float* c, const u32* a, u32 b0, u32 b1) {
    asm volatile("mma.sync.aligned.m16n8k16.row.col.f32.bf16.bf16.f32 "
                 "{%0,%1,%2,%3}, {%4,%5,%6,%7}, {%8,%9}, {%0,%1,%2,%3};"
                 : "+f"(c[0]), "+f"(c[1]), "+f"(c[2]), "+f"(c[3])
                 : "r"(a[0]), "r"(a[1]), "r"(a[2]), "r"(a[3]), "r"(b0), "r"(b1));
}
__device__ __forceinline__ u32 splitpack(float a, float b, u32& lop) {
    bf16 h0 = __float2bfloat16(a), h1 = __float2bfloat16(b);
    bf16 l0 = __float2bfloat16(a - __bfloat162float(h0));
    bf16 l1 = __float2bfloat16(b - __bfloat162float(h1));
    __nv_bfloat162 hv, lv;
    hv.x = h0; hv.y = h1; lv.x = l0; lv.y = l1;
    lop = *(u32*)&lv;
    return *(u32*)&hv;
}

// ---------------- zero small accumulators ----------------
__global__ void zero_k() {
    int t = threadIdx.x;
    g_mean[t] = 0.f; g_mean[t + 256] = 0.f;
    if (t == 0) g_tr = 0.f;
}

// ---------------- split RAW X -> [c][m] AND [m][c]; channel sums via smem phase ----------------
__global__ void conv_fused(const float* __restrict__ X) {
    __shared__ float smf[64][129];
    int b = blockIdx.x;
    int n = b >> 3, hw0 = (b & 7) << 7;
    int tid = threadIdx.x;
    // zero this CTA's Gram slice (gram kernel runs after, same stream)
    for (int p = tid; p < 512; p += 256) g_Gram[(long)b * 512 + p] = 0.f;
    for (int cb = 0; cb < 8; cb++) {
        __syncthreads();
        // streaming load phase — identical structure to proven R14 loop (no reductions inside)
        for (int l = tid; l < 64 * 32; l += 256) {
            int cl = l >> 5, f4 = (l & 31) * 4;
            int ch = cb * 64 + cl;
            float4 v = *(const float4*)&X[(((long)(n * C_DIM + ch)) << 10) + hw0 + f4];
            smf[cl][f4] = v.x; smf[cl][f4 + 1] = v.y;
            smf[cl][f4 + 2] = v.z; smf[cl][f4 + 3] = v.w;
        }
        __syncthreads();
        // channel-sum phase (from smem; shuffles OUTSIDE any load stream)
        {
            int c = tid >> 2, q = tid & 3;
            float s = 0.f;
#pragma unroll 8
            for (int i = 0; i < 32; i++) s += smf[c][q + 4 * i];
            s += __shfl_down_sync(0xFFFFFFFF, s, 2);
            s += __shfl_down_sync(0xFFFFFFFF, s, 1);
            if (q == 0) atomicAdd(&g_mean[cb * 64 + c], s);
        }
        // transposed [m][c] layout
        for (int l = tid; l < 128 * 32; l += 256) {
            int r = l >> 5, j = l & 31;
            u32 lo, hi = splitpack(smf[2 * j][r], smf[2 * j + 1][r], lo);
            long m = (long)n * 1024 + hw0 + r;
            ((u32*)&g_Xth[m * C_DIM])[cb * 32 + j] = hi;
            ((u32*)&g_Xtl[m * C_DIM])[cb * 32 + j] = lo;
        }
        // direct [c][m] layout
        for (int l = tid; l < 64 * 64; l += 256) {
            int cl = l >> 6, p = l & 63;
            u32 lo, hi = splitpack(smf[cl][2 * p], smf[cl][2 * p + 1], lo);
            long c = cb * 64 + cl;
            long u = (c << 15) + ((n * 1024 + hw0) >> 1) + p;
            ((u32*)g_Xh)[u] = hi;
            ((u32*)g_Xl)[u] = lo;
        }
    }
}

// ---------------- gram: tri tiles, warp 64x64/64x32, trace folded into epilogue ----------------
__global__ void __launch_bounds__(256, 1) gram_big(
    const bf16* __restrict__ Ah, const bf16* __restrict__ Al,
    float* __restrict__ outF)
{
    extern __shared__ char sm_raw[];
    u32 sbase = s2u(sm_raw);
    int tid = threadIdx.x, lane = tid & 31, wid = tid >> 5;
    int wm = wid >> 2, wn = wid & 3;
    int t = blockIdx.x;
    bool wide = t < 4;
    const int row0 = c_tr[t], col0 = c_tc[t];
    int z = blockIdx.z;
    int nSteps, s0;
    if (wide) { nSteps = 35 + (z < 9 ? 1 : 0); s0 = z * 35 + (z < 9 ? z : 9); }
    else {
        if (z >= 15) return;
        nSteps = 68 + (z < 4 ? 1 : 0); s0 = z * 68 + (z < 4 ? z : 4);
    }
    long k0 = (long)s0 << 6;

    float c[4][8][4];
#pragma unroll
    for (int mi = 0; mi < 4; mi++)
#pragma unroll
        for (int f = 0; f < 8; f++)
#pragma unroll
            for (int q = 0; q < 4; q++) c[mi][f][q] = 0.f;

    u32 ah[4][4], al[4][4];

    auto load_stage = [&](int st, int ks) {
        u32 sb = sbase + st * STAGE_O;
        long kg = k0 + ((long)ks << 6);
#pragma unroll
        for (int tt = 0; tt < 2; tt++) {
            const bf16* g = tt ? Al : Ah;
#pragma unroll
            for (int rep = 0; rep < 4; rep++) {
                int idx = tid + rep * 256;
                int r = idx >> 3, ch = idx & 7;
                cpasync16(sb + tt * TILE_A + r * ROWB + ch * 16,
                          g + (long)(row0 + r) * M_TOT + kg + ch * 8);
            }
        }
        if (wide) {
#pragma unroll
            for (int tt = 0; tt < 2; tt++) {
                const bf16* g = tt ? Al : Ah;
#pragma unroll
                for (int rep = 0; rep < 8; rep++) {
                    int idx = tid + rep * 256;
                    int r = idx >> 3, ch = idx & 7;
                    cpasync16(sb + OFF_B + tt * TILE_BO + r * ROWB + ch * 16,
                              g + (long)(col0 + r) * M_TOT + kg + ch * 8);
                }
            }
        } else {
#pragma unroll
            for (int tt = 0; tt < 2; tt++) {
                const bf16* g = tt ? Al : Ah;
#pragma unroll
                for (int rep = 0; rep < 4; rep++) {
                    int idx = tid + rep * 256;
                    int r = idx >> 3, ch = idx & 7;
                    cpasync16(sb + OFF_B + tt * TILE_BO + r * ROWB + ch * 16,
                              g + (long)(col0 + r) * M_TOT + kg + ch * 8);
                }
            }
        }
        asm volatile("cp.async.commit_group;");
    };

    load_stage(0, 0);
    load_stage(1, 1);
    asm volatile("cp.async.wait_group 1;" ::: "memory");
    __syncthreads();

    for (int ks = 0; ks < nSteps; ks++) {
        u32 sb = sbase + (ks & 1) * STAGE_O;
#pragma unroll
        for (int kk = 0; kk < 4; kk++) {
            int kcol = kk * 16;
#pragma unroll
            for (int mi = 0; mi < 4; mi++) {
                int r = wm * 64 + mi * 16 + (lane & 15);
                int cb = (kcol + (lane >> 4) * 8) * 2;
                ldm4(ah[mi], sb + 0 * TILE_A + r * ROWB + cb);
                ldm4(al[mi], sb + 1 * TILE_A + r * ROWB + cb);
            }
            if (wide) {
#pragma unroll
                for (int bq = 0; bq < 4; bq++) {
                    u32 bh4[4], bl4[4];
                    int r = wn * 64 + bq * 16 + (lane & 7) + ((lane >> 4) << 3);
                    int cb = (kcol + ((lane >> 3) & 1) * 8) * 2;
                    ldm4(bh4, sb + OFF_B + 0 * TILE_BO + r * ROWB + cb);
                    ldm4(bl4, sb + OFF_B + 1 * TILE_BO + r * ROWB + cb);
#pragma unroll
                    for (int mi = 0; mi < 4; mi++) {
                        mma16816(c[mi][bq * 2],     ah[mi], bh4[0], bh4[1]);
                        mma16816(c[mi][bq * 2 + 1], ah[mi], bh4[2], bh4[3]);
                        mma16816(c[mi][bq * 2],     ah[mi], bl4[0], bl4[1]);
                        mma16816(c[mi][bq * 2 + 1], ah[mi], bl4[2], bl4[3]);
                        mma16816(c[mi][bq * 2],     al[mi], bh4[0], bh4[1]);
                        mma16816(c[mi][bq * 2 + 1], al[mi], bh4[2], bh4[3]);
                    }
                }
            } else {
#pragma unroll
                for (int bq = 0; bq < 2; bq++) {
                    u32 bh4[4], bl4[4];
                    int r = wn * 32 + bq * 16 + (lane & 7) + ((lane >> 4) << 3);
                    int cb = (kcol + ((lane >> 3) & 1) * 8) * 2;
                    ldm4(bh4, sb + OFF_B + 0 * TILE_BO + r * ROWB + cb);
                    ldm4(bl4, sb + OFF_B + 1 * TILE_BO + r * ROWB + cb);
#pragma unroll
                    for (int mi = 0; mi < 4; mi++) {
                        mma16816(c[mi][bq * 2],     ah[mi], bh4[0], bh4[1]);
                        mma16816(c[mi][bq * 2 + 1], ah[mi], bh4[2], bh4[3]);
                        mma16816(c[mi][bq * 2],     ah[mi], bl4[0], bl4[1]);
                        mma16816(c[mi][bq * 2 + 1], ah[mi], bl4[2], bl4[3]);
                        mma16816(c[mi][bq * 2],     al[mi], bh4[0], bh4[1]);
                        mma16816(c[mi][bq * 2 + 1], al[mi], bh4[2], bh4[3]);
                    }
                }
            }
        }
        if (ks + 1 < nSteps) {
            __syncthreads();
            if (ks + 2 < nSteps) {
                load_stage(ks & 1, ks + 2);
                asm volatile("cp.async.wait_group 1;" ::: "memory");
            } else {
                asm volatile("cp.async.wait_group 0;" ::: "memory");
            }
            __syncthreads();
        }
    }

    int rg = lane >> 2, cg = (lane & 3) * 2;
    int nf = wide ? 8 : 4;
    int wstride = wide ? 64 : 32;
#pragma unroll
    for (int mi = 0; mi < 4; mi++)
        for (int f = 0; f < nf; f++) {
            int rr = row0 + wm * 64 + mi * 16 + rg;
            int cc = col0 + wn * wstride + f * 8 + cg;
            atomicAdd(&outF[(long)rr * C_DIM + cc],           c[mi][f][0]);
            atomicAdd(&outF[(long)rr * C_DIM + cc + 1],       c[mi][f][1]);
            atomicAdd(&outF[(long)(rr + 8) * C_DIM + cc],     c[mi][f][2]);
            atomicAdd(&outF[(long)(rr + 8) * C_DIM + cc + 1], c[mi][f][3]);
            if (rr == cc)         atomicAdd(&g_tr, c[mi][f][0]);
            if (rr == cc + 1)     atomicAdd(&g_tr, c[mi][f][1]);
            if (rr + 8 == cc)     atomicAdd(&g_tr, c[mi][f][2]);
            if (rr + 8 == cc + 1) atomicAdd(&g_tr, c[mi][f][3]);
        }
}

// ---------------- out GEMM: CTA 128x256, BK=64, 2-stage, bias-subtract NCHW epilogue ----------------
__global__ void __launch_bounds__(256, 1) gemm_out(
    const bf16* __restrict__ Ah, const bf16* __restrict__ Al,
    const bf16* __restrict__ Bh, const bf16* __restrict__ Bl,
    float* __restrict__ outF)
{
    extern __shared__ char sm_raw[];
    u32 sbase = s2u(sm_raw);
    int tid = threadIdx.x, lane = tid & 31, wid = tid >> 5;
    int wm = wid >> 2, wn = wid & 3;
    const int row0 = blockIdx.x * 128;   // 4 adjacent CTAs share B col-tile in L2
    const int col0 = blockIdx.y * 256;
    const int nSteps = 8;

    float c[4][8][4];
#pragma unroll
    for (int mi = 0; mi < 4; mi++)
#pragma unroll
        for (int f = 0; f < 8; f++)
#pragma unroll
            for (int q = 0; q < 4; q++) c[mi][f][q] = 0.f;

    u32 ah[4][4], al[4][4];

    auto load_stage = [&](int st, int ks) {
        u32 sb = sbase + st * STAGE_O;
        long kg = (long)ks << 6;
#pragma unroll
        for (int t = 0; t < 2; t++) {
            const bf16* g = t ? Al : Ah;
#pragma unroll
            for (int rep = 0; rep < 4; rep++) {
                int idx = tid + rep * 256;
                int r = idx >> 3, ch = idx & 7;
                cpasync16(sb + t * TILE_A + r * ROWB + ch * 16,
                          g + (long)(row0 + r) * C_DIM + kg + ch * 8);
            }
        }
#pragma unroll
        for (int t = 0; t < 2; t++) {
            const bf16* g = t ? Bl : Bh;
#pragma unroll
            for (int rep = 0; rep < 8; rep++) {
                int idx = tid + rep * 256;
                int r = idx >> 3, ch = idx & 7;
                cpasync16(sb + OFF_B + t * TILE_BO + r * ROWB + ch * 16,
                          g + (long)(col0 + r) * C_DIM + kg + ch * 8);
            }
        }
        asm volatile("cp.async.commit_group;");
    };

    load_stage(0, 0);
    load_stage(1, 1);
    asm volatile("cp.async.wait_group 1;" ::: "memory");
    __syncthreads();

    for (int ks = 0; ks < nSteps; ks++) {
        u32 sb = sbase + (ks & 1) * STAGE_O;
#pragma unroll
        for (int kk = 0; kk < 4; kk++) {
            int kcol = kk * 16;
#pragma unroll
            for (int mi = 0; mi < 4; mi++) {
                int r = wm * 64 + mi * 16 + (lane & 15);
                int cb = (kcol + (lane >> 4) * 8) * 2;
                ldm4(ah[mi], sb + 0 * TILE_A + r * ROWB + cb);
                ldm4(al[mi], sb + 1 * TILE_A + r * ROWB + cb);
            }
#pragma unroll
            for (int bq = 0; bq < 4; bq++) {
                u32 bh4[4], bl4[4];
                int r = wn * 64 + bq * 16 + (lane & 7) + ((lane >> 4) << 3);
                int cb = (kcol + ((lane >> 3) & 1) * 8) * 2;
                ldm4(bh4, sb + OFF_B + 0 * TILE_BO + r * ROWB + cb);
                ldm4(bl4, sb + OFF_B + 1 * TILE_BO + r * ROWB + cb);
#pragma unroll
                for (int mi = 0; mi < 4; mi++) {
                    mma16816(c[mi][bq * 2],     ah[mi], bh4[0], bh4[1]);
                    mma16816(c[mi][bq * 2 + 1], ah[mi], bh4[2], bh4[3]);
                    mma16816(c[mi][bq * 2],     ah[mi], bl4[0], bl4[1]);
                    mma16816(c[mi][bq * 2 + 1], ah[mi], bl4[2], bl4[3]);
                    mma16816(c[mi][bq * 2],     al[mi], bh4[0], bh4[1]);
                    mma16816(c[mi][bq * 2 + 1], al[mi], bh4[2], bh4[3]);
                }
            }
        }
        if (ks + 1 < nSteps) {
            __syncthreads();
            if (ks + 2 < nSteps) {
                load_stage(ks & 1, ks + 2);
                asm volatile("cp.async.wait_group 1;" ::: "memory");
            } else {
                asm volatile("cp.async.wait_group 0;" ::: "memory");
            }
            __syncthreads();
        }
    }

    __syncthreads();
    float* st = (float*)sm_raw;
    const int LDS = 260;
    int rg = lane >> 2, cg = (lane & 3) * 2;
#pragma unroll
    for (int mi = 0; mi < 4; mi++)
#pragma unroll
        for (int f = 0; f < 8; f++) {
            int rr = wm * 64 + mi * 16 + rg;
            int cc = wn * 64 + f * 8 + cg;
            st[rr * LDS + cc] = c[mi][f][0];
            st[rr * LDS + cc + 1] = c[mi][f][1];
            st[(rr + 8) * LDS + cc] = c[mi][f][2];
            st[(rr + 8) * LDS + cc + 1] = c[mi][f][3];
        }
    __syncthreads();
    int n = col0 >> 10, hw0 = col0 & 1023;
    for (int l = tid; l < 128 * 64; l += 256) {
        int r = l >> 6, q = l & 63;
        float bb = g_bias[row0 + r];
        float4 v = *(float4*)&st[r * LDS + q * 4];
        v.x -= bb; v.y -= bb; v.z -= bb; v.w -= bb;
        *(float4*)&outF[(((long)(n * C_DIM + row0 + r)) << 10) + hw0 + q * 4] = v;
    }
}

// ---------------- NS GEMM core: 64x64 tile, 256 thr, 2 K-groups (split-K in CTA) ----------------
template<int MODE>   // 2: split write ; 3: NS combine
__device__ __forceinline__ void gemm64_body(
    const bf16* Ah, const bf16* Al, const bf16* Bh, const bf16* Bl,
    const float* Pf, float* Pfn, bf16* outH, bf16* outL, int scaleFlag)
{
    extern __shared__ char sm_raw[];
    u32 sbase = s2u(sm_raw);
    int tid = threadIdx.x, lane = tid & 31, wid = tid >> 5;
    int grp = wid >> 2, wi = wid & 3;
    int wm = wi >> 1, wn = wi & 1;
    int tg = tid & 127;
    const int row0 = blockIdx.y * 64, col0 = blockIdx.x * 64;
    u32 gbase = sbase + grp * (2 * STAGE64G);

    auto barg = [&]() {
        asm volatile("bar.sync %0, %1;" :: "r"(grp + 1), "r"(128) : "memory");
    };

    float c[2][4][4];
#pragma unroll
    for (int mi = 0; mi < 2; mi++)
#pragma unroll
        for (int f = 0; f < 4; f++)
#pragma unroll
            for (int q = 0; q < 4; q++) c[mi][f][q] = 0.f;

    u32 ah[2][2][4], al[2][2][4], bh[2][2][4], bl[2][2][4];

    auto load_stage = [&](int st, int ks) {
        u32 sb = gbase + st * STAGE64G;
        long kg = (long)grp * 256 + ((long)ks << 6);
#pragma unroll
        for (int t = 0; t < 4; t++) {
            const bf16* g = (t == 0) ? Ah : (t == 1) ? Al : (t == 2) ? Bh : Bl;
            long rbase = (t < 2) ? row0 : col0;
#pragma unroll
            for (int rep = 0; rep < 4; rep++) {
                int idx = tg + rep * 128;
                int r = idx >> 3, ch = idx & 7;
                cpasync16(sb + t * TILE64 + r * ROWB + ch * 16,
                          g + (rbase + r) * C_DIM + kg + ch * 8);
            }
        }
        asm volatile("cp.async.commit_group;");
    };
    auto load_frags = [&](int fb, u32 sb, int kk) {
        int kcol = kk * 16;
#pragma unroll
        for (int mi = 0; mi < 2; mi++) {
            int r = wm * 32 + mi * 16 + (lane & 15);
            int cb = (kcol + (lane >> 4) * 8) * 2;
            ldm4(ah[fb][mi], sb + 0 * TILE64 + r * ROWB + cb);
            ldm4(al[fb][mi], sb + 1 * TILE64 + r * ROWB + cb);
        }
#pragma unroll
        for (int nj = 0; nj < 2; nj++) {
            int r = wn * 32 + nj * 16 + (lane & 7) + ((lane >> 4) << 3);
            int cb = (kcol + ((lane >> 3) & 1) * 8) * 2;
            ldm4(bh[fb][nj], sb + 2 * TILE64 + r * ROWB + cb);
            ldm4(bl[fb][nj], sb + 3 * TILE64 + r * ROWB + cb);
        }
    };
    auto mma_all = [&](int fb) {
#pragma unroll
        for (int mi = 0; mi < 2; mi++)
#pragma unroll
            for (int nj = 0; nj < 2; nj++) {
                mma16816(c[mi][nj * 2],     ah[fb][mi], bh[fb][nj][0], bh[fb][nj][1]);
                mma16816(c[mi][nj * 2 + 1], ah[fb][mi], bh[fb][nj][2], bh[fb][nj][3]);
                mma16816(c[mi][nj * 2],     ah[fb][mi], bl[fb][nj][0], bl[fb][nj][1]);
                mma16816(c[mi][nj * 2 + 1], ah[fb][mi], bl[fb][nj][2], bl[fb][nj][3]);
                mma16816(c[mi][nj * 2],     al[fb][mi], bh[fb][nj][0], bh[fb][nj][1]);
                mma16816(c[mi][nj * 2 + 1], al[fb][mi], bh[fb][nj][2], bh[fb][nj][3]);
            }
    };

    load_stage(0, 0);
    load_stage(1, 1);
    asm volatile("cp.async.wait_group 1;" ::: "memory");
    barg();
    load_frags(0, gbase, 0);

    for (int ks = 0; ks < 4; ks++) {
        u32 sb = gbase + (ks & 1) * STAGE64G;
#pragma unroll
        for (int kk = 0; kk < 4; kk++) {
            if (kk < 3) load_frags((kk + 1) & 1, sb, kk + 1);
            mma_all(kk & 1);
        }
        if (ks + 1 < 4) {
            barg();
            if (ks + 2 < 4) {
                load_stage(ks & 1, ks + 2);
                asm volatile("cp.async.wait_group 1;" ::: "memory");
            } else {
                asm volatile("cp.async.wait_group 0;" ::: "memory");
            }
            barg();
            load_frags(0, gbase + ((ks + 1) & 1) * STAGE64G, 0);
        }
    }

    float* red = (float*)sm_raw;
    int rg = lane >> 2, cg = (lane & 3) * 2;
    __syncthreads();
    if (grp == 1) {
#pragma unroll
        for (int mi = 0; mi < 2; mi++)
#pragma unroll
            for (int f = 0; f < 4; f++) {
                int lrr = wm * 32 + mi * 16 + rg;
                int lcc = wn * 32 + (f >> 1) * 16 + (f & 1) * 8 + cg;
#pragma unroll
                for (int half = 0; half < 2; half++) {
                    red[(lrr + half * 8) * 64 + lcc]     = c[mi][f][half * 2];
                    red[(lrr + half * 8) * 64 + lcc + 1] = c[mi][f][half * 2 + 1];
                }
            }
    }
    __syncthreads();
    if (grp == 0) {
        float sc = (MODE == 3 && scaleFlag) ? sqrtf(g_rTr) : 1.f;
#pragma unroll
        for (int mi = 0; mi < 2; mi++)
#pragma unroll
            for (int f = 0; f < 4; f++) {
                int lrr = wm * 32 + mi * 16 + rg;
                int lcc = wn * 32 + (f >> 1) * 16 + (f & 1) * 8 + cg;
#pragma unroll
                for (int half = 0; half < 2; half++) {
                    int r2 = row0 + lrr + half * 8;
                    int cc = col0 + lcc;
                    float v0 = c[mi][f][half * 2]     + red[(lrr + half * 8) * 64 + lcc];
                    float v1 = c[mi][f][half * 2 + 1] + red[(lrr + half * 8) * 64 + lcc + 1];
                    long fi = (long)r2 * C_DIM + cc;
                    if (MODE == 3) {
                        v0 = fmaf(-0.5f, v0, 1.5f * Pf[fi]);
                        v1 = fmaf(-0.5f, v1, 1.5f * Pf[fi + 1]);
                        Pfn[fi] = v0; Pfn[fi + 1] = v1;
                        v0 *= sc; v1 *= sc;
                    }
                    u32 lo, hi = splitpack(v0, v1, lo);
                    ((u32*)outH)[fi >> 1] = hi;
                    ((u32*)outL)[fi >> 1] = lo;
                }
            }
    }
}

__global__ void __launch_bounds__(256, 1) gemm64_pair(
    const bf16* __restrict__ Ph, const bf16* __restrict__ Pl,
    const bf16* __restrict__ Sh, const bf16* __restrict__ Sl)
{
    if (blockIdx.z == 0)
        gemm64_body<2>(Ph, Pl, Ph, Pl, nullptr, nullptr, g_T1h, g_T1l, 0);
    else
        gemm64_body<2>(Ph, Pl, Sh, Sl, nullptr, nullptr, g_Uh, g_Ul, 0);
}

__global__ void __launch_bounds__(256, 1) gemm64_comb(
    const float* __restrict__ Pf, float* __restrict__ Pfn,
    bf16* __restrict__ outH, bf16* __restrict__ outL, int scaleFlag)
{
    gemm64_body<3>(g_T1h, g_T1l, g_Uh, g_Ul, Pf, Pfn, outH, outL, scaleFlag);
}

// ---------------- Sigma_N split (mirrored read, rank-1 mean fixup) + P1 ----------------
__global__ void finalize_k() {
    __shared__ float sred[256];
    int i = blockIdx.x;
    int j2 = threadIdx.x;
    int j = j2 * 2;
    float mu0 = g_mean[j] * INV_M, mu1 = g_mean[j + 1] * INV_M;
    sred[j2] = mu0 * mu0 + mu1 * mu1;
    __syncthreads();
    for (int off = 128; off > 0; off >>= 1) {
        if (j2 < off) sred[j2] += sred[j2 + off];
        __syncthreads();
    }
    float munorm = sred[0];
    float rtr = 1.0f / (g_tr * INV_M - munorm + (float)C_DIM * EPS_V);
    if (i == 0 && j2 == 0) g_rTr = rtr;

    float mui = g_mean[i] * INV_M;
    int bi = i >> 7;
    float r0 = (bi <= (j >> 7)) ? g_Gram[(long)i * C_DIM + j] : g_Gram[(long)j * C_DIM + i];
    float r1 = (bi <= ((j + 1) >> 7)) ? g_Gram[(long)i * C_DIM + j + 1] : g_Gram[(long)(j + 1) * C_DIM + i];
    float s0 = r0 * INV_M - mui * mu0;
    float s1 = r1 * INV_M - mui * mu1;
    if (i == j) s0 += EPS_V;
    if (i == j + 1) s1 += EPS_V;
    s0 *= rtr; s1 *= rtr;
    u32 lo, hi = splitpack(s0, s1, lo);
    ((u32*)g_Sh)[i * 256 + j2] = hi; ((u32*)g_Sl)[i * 256 + j2] = lo;
    float p0 = ((i == j) ? 1.5f : 0.f) - 0.5f * s0;
    float p1 = ((i == j + 1) ? 1.5f : 0.f) - 0.5f * s1;
    g_PfA[(long)i * C_DIM + j] = p0;
    g_PfA[(long)i * C_DIM + j + 1] = p1;
    hi = splitpack(p0, p1, lo);
    ((u32*)g_PAh)[i * 256 + j2] = hi; ((u32*)g_PAl)[i * 256 + j2] = lo;
}

// ---------------- bias[r] = sqrt(rTr) * dot(P5[r,:], mu) ----------------
__global__ void bias_k(const float* __restrict__ Pf) {
    __shared__ float sred[128];
    int r = blockIdx.x;
    float s = 0.f;
    for (int j = threadIdx.x; j < C_DIM; j += 128)
        s += Pf[(long)r * C_DIM + j] * g_mean[j];
    sred[threadIdx.x] = s;
    __syncthreads();
    for (int off = 64; off > 0; off >>= 1) {
        if (threadIdx.x < off) sred[threadIdx.x] += sred[threadIdx.x + off];
        __syncthreads();
    }
    if (threadIdx.x == 0)
        g_bias[r] = sqrtf(g_rTr) * sred[0] * INV_M;
}

// ---------------- launch ----------------
extern "C" void kernel_launch(void* const* d_in, const int* in_sizes, int n_in,
                              void* d_out, int out_size) {
    const float* X = (const float*)d_in[0];
    float* Out = (float*)d_out;

    cudaFuncSetAttribute(gram_big, cudaFuncAttributeMaxDynamicSharedMemorySize, GSMEM_O);
    cudaFuncSetAttribute(gemm_out, cudaFuncAttributeMaxDynamicSharedMemorySize, GSMEM_O);
    cudaFuncSetAttribute(gemm64_pair, cudaFuncAttributeMaxDynamicSharedMemorySize, NS_SMEM);
    cudaFuncSetAttribute(gemm64_comb, cudaFuncAttributeMaxDynamicSharedMemorySize, NS_SMEM);

    void *xh, *xl, *xth, *xtl, *sh, *sl, *pah, *pal, *pbh, *pbl;
    void *wh, *wl, *pfa, *pfb, *gram;
    cudaGetSymbolAddress(&xh, g_Xh);   cudaGetSymbolAddress(&xl, g_Xl);
    cudaGetSymbolAddress(&xth, g_Xth); cudaGetSymbolAddress(&xtl, g_Xtl);
    cudaGetSymbolAddress(&sh, g_Sh);   cudaGetSymbolAddress(&sl, g_Sl);
    cudaGetSymbolAddress(&pah, g_PAh); cudaGetSymbolAddress(&pal, g_PAl);
    cudaGetSymbolAddress(&pbh, g_PBh); cudaGetSymbolAddress(&pbl, g_PBl);
    cudaGetSymbolAddress(&wh, g_Wh);   cudaGetSymbolAddress(&wl, g_Wl);
    cudaGetSymbolAddress(&pfa, g_PfA); cudaGetSymbolAddress(&pfb, g_PfB);
    cudaGetSymbolAddress(&gram, g_Gram);

    zero_k<<<1, 256>>>();
    conv_fused<<<512, 256>>>(X);

    // Gram_raw = X X^T, tri tiles + uneven K split; trace folded into epilogue
    gram_big<<<dim3(6, 1, 29), 256, GSMEM_O>>>(
        (const bf16*)xh, (const bf16*)xl, (float*)gram);

    finalize_k<<<C_DIM, 256>>>();

    // Newton-Schulz iterations 2..5 (iter 1 folded into finalize_k)
    float *pfc = (float*)pfa, *pfn = (float*)pfb;
    bf16 *pch = (bf16*)pah, *pcl = (bf16*)pal, *pnh = (bf16*)pbh, *pnl = (bf16*)pbl;
    for (int it = 0; it < 4; it++) {
        int last = (it == 3);
        gemm64_pair<<<dim3(8, 8, 2), 256, NS_SMEM>>>(pch, pcl, (const bf16*)sh, (const bf16*)sl);
        gemm64_comb<<<dim3(8, 8), 256, NS_SMEM>>>(
            pfc, pfn, last ? (bf16*)wh : pnh, last ? (bf16*)wl : pnl, last);
        float* tf = pfc; pfc = pfn; pfn = tf;
        bf16* th = pch; pch = pnh; pnh = th;
        bf16* tl = pcl; pcl = pnl; pnl = tl;
    }

    bias_k<<<C_DIM, 128>>>(pfc);

    // Out[c][m] = W @ X - bias, written NCHW
    gemm_out<<<dim3(4, 256), 256, GSMEM_O>>>(
        (const bf16*)wh, (const bf16*)wl,
        (const bf16*)xth, (const bf16*)xtl, Out);
}

// round 16
// speedup vs baseline: 1.0410x; 1.0410x over previous
#include <cuda_runtime.h>
#include <cuda_bf16.h>
#include <stdint.h>
#include <math.h>

typedef __nv_bfloat16 bf16;
typedef unsigned int u32;

#define C_DIM 512
#define M_TOT 65536
#define INV_M (1.0f / 65536.0f)
#define EPS_V 1e-5f

#define ROWB 144                 // 64 bf16 = 128B data + 16B pad
// 128x256 tiling (gram_big + gemm_out): BK=64, 8 warps (2x4), warp 64x64
#define TILE_A (128 * ROWB)      // 18432
#define TILE_BO (256 * ROWB)     // 36864
#define OFF_B (2 * TILE_A)       // 36864
#define STAGE_O (2 * TILE_A + 2 * TILE_BO)  // 110592
#define GSMEM_O (2 * STAGE_O)    // 221184

// NS tiling: CTA 64x64, 256 threads, 2 K-groups of 4 warps
#define TILE64 (64 * ROWB)       // 9216
#define STAGE64G (4 * TILE64)    // 36864
#define NS_SMEM (4 * STAGE64G)   // 147456

// gram tri tiling: 4 wide (128x256) + 2 narrow (128x128) tiles
__constant__ int c_tr[6] = {0, 0, 128, 256, 128, 384};
__constant__ int c_tc[6] = {0, 256, 256, 256, 128, 384};

// ---------------- scratch ----------------
__device__ float g_mean[C_DIM];
__device__ float g_Gram[C_DIM * C_DIM];
__device__ float g_rTr;
__device__ float g_tr;
__device__ bf16 g_Xh[33554432];   // centered X, [c][m]
__device__ bf16 g_Xl[33554432];
__device__ bf16 g_Xth[33554432];  // centered X, [m][c]
__device__ bf16 g_Xtl[33554432];
__device__ bf16 g_Sh[C_DIM * C_DIM], g_Sl[C_DIM * C_DIM];
__device__ bf16 g_PAh[C_DIM * C_DIM], g_PAl[C_DIM * C_DIM];
__device__ bf16 g_PBh[C_DIM * C_DIM], g_PBl[C_DIM * C_DIM];
__device__ bf16 g_T1h[C_DIM * C_DIM], g_T1l[C_DIM * C_DIM];
__device__ bf16 g_Uh[C_DIM * C_DIM], g_Ul[C_DIM * C_DIM];
__device__ bf16 g_Wh[C_DIM * C_DIM], g_Wl[C_DIM * C_DIM];
__device__ float g_PfA[C_DIM * C_DIM], g_PfB[C_DIM * C_DIM];

// ---------------- helpers ----------------
__device__ __forceinline__ u32 s2u(const void* p) {
    u32 a;
    asm("{ .reg .u64 t; cvta.to.shared.u64 t, %1; cvt.u32.u64 %0, t; }" : "=r"(a) : "l"(p));
    return a;
}
__device__ __forceinline__ void cpasync16(u32 dst, const void* src) {
    asm volatile("cp.async.cg.shared.global [%0], [%1], 16;" :: "r"(dst), "l"(src));
}
__device__ __forceinline__ void ldm4(u32* r, u32 addr) {
    asm volatile("ldmatrix.sync.aligned.m8n8.x4.shared.b16 {%0,%1,%2,%3}, [%4];"
                 : "=r"(r[0]), "=r"(r[1]), "=r"(r[2]), "=r"(r[3]) : "r"(addr));
}
__device__ __forceinline__ void mma16816(float* c, const u32* a, u32 b0, u32 b1) {
    asm volatile("mma.sync.aligned.m16n8k16.row.col.f32.bf16.bf16.f32 "
                 "{%0,%1,%2,%3}, {%4,%5,%6,%7}, {%8,%9}, {%0,%1,%2,%3};"
                 : "+f"(c[0]), "+f"(c[1]), "+f"(c[2]), "+f"(c[3])
                 : "r"(a[0]), "r"(a[1]), "r"(a[2]), "r"(a[3]), "r"(b0), "r"(b1));
}
__device__ __forceinline__ u32 splitpack(float a, float b, u32& lop) {
    bf16 h0 = __float2bfloat16(a), h1 = __float2bfloat16(b);
    bf16 l0 = __float2bfloat16(a - __bfloat162float(h0));
    bf16 l1 = __float2bfloat16(b - __bfloat162float(h1));
    __nv_bfloat162 hv, lv;
    hv.x = h0; hv.y = h1; lv.x = l0; lv.y = l1;
    lop = *(u32*)&lv;
    return *(u32*)&hv;
}

// ---------------- mean per channel + zero Gram + zero trace ----------------
__global__ void mean_kernel(const float* __restrict__ X) {
    int c = blockIdx.x;
    float s = 0.f;
    for (int idx = threadIdx.x; idx < (M_TOT / 4); idx += 256) {
        int n = idx >> 8, h4 = idx & 255;
        const float4 v = *(const float4*)&X[(((size_t)(n * C_DIM + c)) << 10) + (size_t)h4 * 4];
        s += (v.x + v.y) + (v.z + v.w);
    }
    __shared__ float red[256];
    red[threadIdx.x] = s;
    __syncthreads();
    for (int off = 128; off > 0; off >>= 1) {
        if (threadIdx.x < off) red[threadIdx.x] += red[threadIdx.x + off];
        __syncthreads();
    }
    if (threadIdx.x == 0) g_mean[c] = red[0] * INV_M;
    for (int j = threadIdx.x; j < C_DIM; j += 256) g_Gram[(long)c * C_DIM + j] = 0.f;
    if (c == 0 && threadIdx.x == 0) g_tr = 0.f;
}

// ---------------- fused center+split: X -> [c][m] AND [m][c] layouts ----------------
__global__ void conv_fused(const float* __restrict__ X) {
    __shared__ float smf[64][129];
    int b = blockIdx.x;
    int n = b >> 3, hw0 = (b & 7) << 7;
    int tid = threadIdx.x;
    for (int cb = 0; cb < 8; cb++) {
        __syncthreads();
        for (int l = tid; l < 64 * 32; l += 256) {
            int cl = l >> 5, f4 = (l & 31) * 4;
            int ch = cb * 64 + cl;
            float4 v = *(const float4*)&X[(((long)(n * C_DIM + ch)) << 10) + hw0 + f4];
            float mu = g_mean[ch];
            smf[cl][f4] = v.x - mu; smf[cl][f4 + 1] = v.y - mu;
            smf[cl][f4 + 2] = v.z - mu; smf[cl][f4 + 3] = v.w - mu;
        }
        __syncthreads();
        for (int l = tid; l < 128 * 32; l += 256) {
            int r = l >> 5, j = l & 31;
            u32 lo, hi = splitpack(smf[2 * j][r], smf[2 * j + 1][r], lo);
            long m = (long)n * 1024 + hw0 + r;
            ((u32*)&g_Xth[m * C_DIM])[cb * 32 + j] = hi;
            ((u32*)&g_Xtl[m * C_DIM])[cb * 32 + j] = lo;
        }
        for (int l = tid; l < 64 * 64; l += 256) {
            int cl = l >> 6, p = l & 63;
            u32 lo, hi = splitpack(smf[cl][2 * p], smf[cl][2 * p + 1], lo);
            long c = cb * 64 + cl;
            long u = (c << 15) + ((n * 1024 + hw0) >> 1) + p;
            ((u32*)g_Xh)[u] = hi;
            ((u32*)g_Xl)[u] = lo;
        }
    }
}

// ---------------- gram: tri tiles, warp 64x64/64x32, trace folded into epilogue ----------------
__global__ void __launch_bounds__(256, 1) gram_big(
    const bf16* __restrict__ Ah, const bf16* __restrict__ Al,
    float* __restrict__ outF)
{
    extern __shared__ char sm_raw[];
    u32 sbase = s2u(sm_raw);
    int tid = threadIdx.x, lane = tid & 31, wid = tid >> 5;
    int wm = wid >> 2, wn = wid & 3;
    int t = blockIdx.x;
    bool wide = t < 4;
    const int row0 = c_tr[t], col0 = c_tc[t];
    int z = blockIdx.z;
    int nSteps, s0;
    if (wide) { nSteps = 35 + (z < 9 ? 1 : 0); s0 = z * 35 + (z < 9 ? z : 9); }
    else {
        if (z >= 15) return;
        nSteps = 68 + (z < 4 ? 1 : 0); s0 = z * 68 + (z < 4 ? z : 4);
    }
    long k0 = (long)s0 << 6;

    float c[4][8][4];
#pragma unroll
    for (int mi = 0; mi < 4; mi++)
#pragma unroll
        for (int f = 0; f < 8; f++)
#pragma unroll
            for (int q = 0; q < 4; q++) c[mi][f][q] = 0.f;

    u32 ah[4][4], al[4][4];

    auto load_stage = [&](int st, int ks) {
        u32 sb = sbase + st * STAGE_O;
        long kg = k0 + ((long)ks << 6);
#pragma unroll
        for (int tt = 0; tt < 2; tt++) {
            const bf16* g = tt ? Al : Ah;
#pragma unroll
            for (int rep = 0; rep < 4; rep++) {
                int idx = tid + rep * 256;
                int r = idx >> 3, ch = idx & 7;
                cpasync16(sb + tt * TILE_A + r * ROWB + ch * 16,
                          g + (long)(row0 + r) * M_TOT + kg + ch * 8);
            }
        }
        if (wide) {
#pragma unroll
            for (int tt = 0; tt < 2; tt++) {
                const bf16* g = tt ? Al : Ah;
#pragma unroll
                for (int rep = 0; rep < 8; rep++) {
                    int idx = tid + rep * 256;
                    int r = idx >> 3, ch = idx & 7;
                    cpasync16(sb + OFF_B + tt * TILE_BO + r * ROWB + ch * 16,
                              g + (long)(col0 + r) * M_TOT + kg + ch * 8);
                }
            }
        } else {
#pragma unroll
            for (int tt = 0; tt < 2; tt++) {
                const bf16* g = tt ? Al : Ah;
#pragma unroll
                for (int rep = 0; rep < 4; rep++) {
                    int idx = tid + rep * 256;
                    int r = idx >> 3, ch = idx & 7;
                    cpasync16(sb + OFF_B + tt * TILE_BO + r * ROWB + ch * 16,
                              g + (long)(col0 + r) * M_TOT + kg + ch * 8);
                }
            }
        }
        asm volatile("cp.async.commit_group;");
    };

    load_stage(0, 0);
    load_stage(1, 1);
    asm volatile("cp.async.wait_group 1;" ::: "memory");
    __syncthreads();

    for (int ks = 0; ks < nSteps; ks++) {
        u32 sb = sbase + (ks & 1) * STAGE_O;
#pragma unroll
        for (int kk = 0; kk < 4; kk++) {
            int kcol = kk * 16;
#pragma unroll
            for (int mi = 0; mi < 4; mi++) {
                int r = wm * 64 + mi * 16 + (lane & 15);
                int cb = (kcol + (lane >> 4) * 8) * 2;
                ldm4(ah[mi], sb + 0 * TILE_A + r * ROWB + cb);
                ldm4(al[mi], sb + 1 * TILE_A + r * ROWB + cb);
            }
            if (wide) {
#pragma unroll
                for (int bq = 0; bq < 4; bq++) {
                    u32 bh4[4], bl4[4];
                    int r = wn * 64 + bq * 16 + (lane & 7) + ((lane >> 4) << 3);
                    int cb = (kcol + ((lane >> 3) & 1) * 8) * 2;
                    ldm4(bh4, sb + OFF_B + 0 * TILE_BO + r * ROWB + cb);
                    ldm4(bl4, sb + OFF_B + 1 * TILE_BO + r * ROWB + cb);
#pragma unroll
                    for (int mi = 0; mi < 4; mi++) {
                        mma16816(c[mi][bq * 2],     ah[mi], bh4[0], bh4[1]);
                        mma16816(c[mi][bq * 2 + 1], ah[mi], bh4[2], bh4[3]);
                        mma16816(c[mi][bq * 2],     ah[mi], bl4[0], bl4[1]);
                        mma16816(c[mi][bq * 2 + 1], ah[mi], bl4[2], bl4[3]);
                        mma16816(c[mi][bq * 2],     al[mi], bh4[0], bh4[1]);
                        mma16816(c[mi][bq * 2 + 1], al[mi], bh4[2], bh4[3]);
                    }
                }
            } else {
#pragma unroll
                for (int bq = 0; bq < 2; bq++) {
                    u32 bh4[4], bl4[4];
                    int r = wn * 32 + bq * 16 + (lane & 7) + ((lane >> 4) << 3);
                    int cb = (kcol + ((lane >> 3) & 1) * 8) * 2;
                    ldm4(bh4, sb + OFF_B + 0 * TILE_BO + r * ROWB + cb);
                    ldm4(bl4, sb + OFF_B + 1 * TILE_BO + r * ROWB + cb);
#pragma unroll
                    for (int mi = 0; mi < 4; mi++) {
                        mma16816(c[mi][bq * 2],     ah[mi], bh4[0], bh4[1]);
                        mma16816(c[mi][bq * 2 + 1], ah[mi], bh4[2], bh4[3]);
                        mma16816(c[mi][bq * 2],     ah[mi], bl4[0], bl4[1]);
                        mma16816(c[mi][bq * 2 + 1], ah[mi], bl4[2], bl4[3]);
                        mma16816(c[mi][bq * 2],     al[mi], bh4[0], bh4[1]);
                        mma16816(c[mi][bq * 2 + 1], al[mi], bh4[2], bh4[3]);
                    }
                }
            }
        }
        if (ks + 1 < nSteps) {
            __syncthreads();
            if (ks + 2 < nSteps) {
                load_stage(ks & 1, ks + 2);
                asm volatile("cp.async.wait_group 1;" ::: "memory");
            } else {
                asm volatile("cp.async.wait_group 0;" ::: "memory");
            }
            __syncthreads();
        }
    }

    int rg = lane >> 2, cg = (lane & 3) * 2;
    int nf = wide ? 8 : 4;
    int wstride = wide ? 64 : 32;
#pragma unroll
    for (int mi = 0; mi < 4; mi++)
        for (int f = 0; f < nf; f++) {
            int rr = row0 + wm * 64 + mi * 16 + rg;
            int cc = col0 + wn * wstride + f * 8 + cg;
            atomicAdd(&outF[(long)rr * C_DIM + cc],           c[mi][f][0]);
            atomicAdd(&outF[(long)rr * C_DIM + cc + 1],       c[mi][f][1]);
            atomicAdd(&outF[(long)(rr + 8) * C_DIM + cc],     c[mi][f][2]);
            atomicAdd(&outF[(long)(rr + 8) * C_DIM + cc + 1], c[mi][f][3]);
            if (rr == cc)         atomicAdd(&g_tr, c[mi][f][0]);
            if (rr == cc + 1)     atomicAdd(&g_tr, c[mi][f][1]);
            if (rr + 8 == cc)     atomicAdd(&g_tr, c[mi][f][2]);
            if (rr + 8 == cc + 1) atomicAdd(&g_tr, c[mi][f][3]);
        }
}

// ---------------- out GEMM: CTA 128x256, BK=64, 2-stage, L2-friendly grid, NCHW epilogue ----------------
__global__ void __launch_bounds__(256, 1) gemm_out(
    const bf16* __restrict__ Ah, const bf16* __restrict__ Al,
    const bf16* __restrict__ Bh, const bf16* __restrict__ Bl,
    float* __restrict__ outF)
{
    extern __shared__ char sm_raw[];
    u32 sbase = s2u(sm_raw);
    int tid = threadIdx.x, lane = tid & 31, wid = tid >> 5;
    int wm = wid >> 2, wn = wid & 3;
    const int row0 = blockIdx.x * 128;   // 4 adjacent CTAs share B col-tile in L2
    const int col0 = blockIdx.y * 256;
    const int nSteps = 8;

    float c[4][8][4];
#pragma unroll
    for (int mi = 0; mi < 4; mi++)
#pragma unroll
        for (int f = 0; f < 8; f++)
#pragma unroll
            for (int q = 0; q < 4; q++) c[mi][f][q] = 0.f;

    u32 ah[4][4], al[4][4];

    auto load_stage = [&](int st, int ks) {
        u32 sb = sbase + st * STAGE_O;
        long kg = (long)ks << 6;
#pragma unroll
        for (int t = 0; t < 2; t++) {
            const bf16* g = t ? Al : Ah;
#pragma unroll
            for (int rep = 0; rep < 4; rep++) {
                int idx = tid + rep * 256;
                int r = idx >> 3, ch = idx & 7;
                cpasync16(sb + t * TILE_A + r * ROWB + ch * 16,
                          g + (long)(row0 + r) * C_DIM + kg + ch * 8);
            }
        }
#pragma unroll
        for (int t = 0; t < 2; t++) {
            const bf16* g = t ? Bl : Bh;
#pragma unroll
            for (int rep = 0; rep < 8; rep++) {
                int idx = tid + rep * 256;
                int r = idx >> 3, ch = idx & 7;
                cpasync16(sb + OFF_B + t * TILE_BO + r * ROWB + ch * 16,
                          g + (long)(col0 + r) * C_DIM + kg + ch * 8);
            }
        }
        asm volatile("cp.async.commit_group;");
    };

    load_stage(0, 0);
    load_stage(1, 1);
    asm volatile("cp.async.wait_group 1;" ::: "memory");
    __syncthreads();

    for (int ks = 0; ks < nSteps; ks++) {
        u32 sb = sbase + (ks & 1) * STAGE_O;
#pragma unroll
        for (int kk = 0; kk < 4; kk++) {
            int kcol = kk * 16;
#pragma unroll
            for (int mi = 0; mi < 4; mi++) {
                int r = wm * 64 + mi * 16 + (lane & 15);
                int cb = (kcol + (lane >> 4) * 8) * 2;
                ldm4(ah[mi], sb + 0 * TILE_A + r * ROWB + cb);
                ldm4(al[mi], sb + 1 * TILE_A + r * ROWB + cb);
            }
#pragma unroll
            for (int bq = 0; bq < 4; bq++) {
                u32 bh4[4], bl4[4];
                int r = wn * 64 + bq * 16 + (lane & 7) + ((lane >> 4) << 3);
                int cb = (kcol + ((lane >> 3) & 1) * 8) * 2;
                ldm4(bh4, sb + OFF_B + 0 * TILE_BO + r * ROWB + cb);
                ldm4(bl4, sb + OFF_B + 1 * TILE_BO + r * ROWB + cb);
#pragma unroll
                for (int mi = 0; mi < 4; mi++) {
                    mma16816(c[mi][bq * 2],     ah[mi], bh4[0], bh4[1]);
                    mma16816(c[mi][bq * 2 + 1], ah[mi], bh4[2], bh4[3]);
                    mma16816(c[mi][bq * 2],     ah[mi], bl4[0], bl4[1]);
                    mma16816(c[mi][bq * 2 + 1], ah[mi], bl4[2], bl4[3]);
                    mma16816(c[mi][bq * 2],     al[mi], bh4[0], bh4[1]);
                    mma16816(c[mi][bq * 2 + 1], al[mi], bh4[2], bh4[3]);
                }
            }
        }
        if (ks + 1 < nSteps) {
            __syncthreads();
            if (ks + 2 < nSteps) {
                load_stage(ks & 1, ks + 2);
                asm volatile("cp.async.wait_group 1;" ::: "memory");
            } else {
                asm volatile("cp.async.wait_group 0;" ::: "memory");
            }
            __syncthreads();
        }
    }

    __syncthreads();
    float* st = (float*)sm_raw;
    const int LDS = 260;
    int rg = lane >> 2, cg = (lane & 3) * 2;
#pragma unroll
    for (int mi = 0; mi < 4; mi++)
#pragma unroll
        for (int f = 0; f < 8; f++) {
            int rr = wm * 64 + mi * 16 + rg;
            int cc = wn * 64 + f * 8 + cg;
            st[rr * LDS + cc] = c[mi][f][0];
            st[rr * LDS + cc + 1] = c[mi][f][1];
            st[(rr + 8) * LDS + cc] = c[mi][f][2];
            st[(rr + 8) * LDS + cc + 1] = c[mi][f][3];
        }
    __syncthreads();
    int n = col0 >> 10, hw0 = col0 & 1023;
    for (int l = tid; l < 128 * 64; l += 256) {
        int r = l >> 6, q = l & 63;
        float4 v = *(float4*)&st[r * LDS + q * 4];
        *(float4*)&outF[(((long)(n * C_DIM + row0 + r)) << 10) + hw0 + q * 4] = v;
    }
}

// ---------------- NS GEMM core: 64x64 tile, 256 thr, 2 K-groups; FAST = hi-only products ----------------
template<int MODE, int FAST>   // MODE 2: split write ; 3: NS combine
__device__ __forceinline__ void gemm64_body(
    const bf16* Ah, const bf16* Al, const bf16* Bh, const bf16* Bl,
    const float* Pf, float* Pfn, bf16* outH, bf16* outL, int scaleFlag)
{
    extern __shared__ char sm_raw[];
    u32 sbase = s2u(sm_raw);
    int tid = threadIdx.x, lane = tid & 31, wid = tid >> 5;
    int grp = wid >> 2, wi = wid & 3;
    int wm = wi >> 1, wn = wi & 1;
    int tg = tid & 127;
    const int row0 = blockIdx.y * 64, col0 = blockIdx.x * 64;
    u32 gbase = sbase + grp * (2 * STAGE64G);

    auto barg = [&]() {
        asm volatile("bar.sync %0, %1;" :: "r"(grp + 1), "r"(128) : "memory");
    };

    float c[2][4][4];
#pragma unroll
    for (int mi = 0; mi < 2; mi++)
#pragma unroll
        for (int f = 0; f < 4; f++)
#pragma unroll
            for (int q = 0; q < 4; q++) c[mi][f][q] = 0.f;

    u32 ah[2][2][4], al[2][2][4], bh[2][2][4], bl[2][2][4];

    auto load_stage = [&](int st, int ks) {
        u32 sb = gbase + st * STAGE64G;
        long kg = (long)grp * 256 + ((long)ks << 6);
#pragma unroll
        for (int t = 0; t < 4; t++) {
            if (FAST && (t == 1 || t == 3)) continue;
            const bf16* g = (t == 0) ? Ah : (t == 1) ? Al : (t == 2) ? Bh : Bl;
            long rbase = (t < 2) ? row0 : col0;
#pragma unroll
            for (int rep = 0; rep < 4; rep++) {
                int idx = tg + rep * 128;
                int r = idx >> 3, ch = idx & 7;
                cpasync16(sb + t * TILE64 + r * ROWB + ch * 16,
                          g + (rbase + r) * C_DIM + kg + ch * 8);
            }
        }
        asm volatile("cp.async.commit_group;");
    };
    auto load_frags = [&](int fb, u32 sb, int kk) {
        int kcol = kk * 16;
#pragma unroll
        for (int mi = 0; mi < 2; mi++) {
            int r = wm * 32 + mi * 16 + (lane & 15);
            int cb = (kcol + (lane >> 4) * 8) * 2;
            ldm4(ah[fb][mi], sb + 0 * TILE64 + r * ROWB + cb);
            if (!FAST) ldm4(al[fb][mi], sb + 1 * TILE64 + r * ROWB + cb);
        }
#pragma unroll
        for (int nj = 0; nj < 2; nj++) {
            int r = wn * 32 + nj * 16 + (lane & 7) + ((lane >> 4) << 3);
            int cb = (kcol + ((lane >> 3) & 1) * 8) * 2;
            ldm4(bh[fb][nj], sb + 2 * TILE64 + r * ROWB + cb);
            if (!FAST) ldm4(bl[fb][nj], sb + 3 * TILE64 + r * ROWB + cb);
        }
    };
    auto mma_all = [&](int fb) {
#pragma unroll
        for (int mi = 0; mi < 2; mi++)
#pragma unroll
            for (int nj = 0; nj < 2; nj++) {
                mma16816(c[mi][nj * 2],     ah[fb][mi], bh[fb][nj][0], bh[fb][nj][1]);
                mma16816(c[mi][nj * 2 + 1], ah[fb][mi], bh[fb][nj][2], bh[fb][nj][3]);
                if (!FAST) {
                    mma16816(c[mi][nj * 2],     ah[fb][mi], bl[fb][nj][0], bl[fb][nj][1]);
                    mma16816(c[mi][nj * 2 + 1], ah[fb][mi], bl[fb][nj][2], bl[fb][nj][3]);
                    mma16816(c[mi][nj * 2],     al[fb][mi], bh[fb][nj][0], bh[fb][nj][1]);
                    mma16816(c[mi][nj * 2 + 1], al[fb][mi], bh[fb][nj][2], bh[fb][nj][3]);
                }
            }
    };

    load_stage(0, 0);
    load_stage(1, 1);
    asm volatile("cp.async.wait_group 1;" ::: "memory");
    barg();
    load_frags(0, gbase, 0);

    for (int ks = 0; ks < 4; ks++) {
        u32 sb = gbase + (ks & 1) * STAGE64G;
#pragma unroll
        for (int kk = 0; kk < 4; kk++) {
            if (kk < 3) load_frags((kk + 1) & 1, sb, kk + 1);
            mma_all(kk & 1);
        }
        if (ks + 1 < 4) {
            barg();
            if (ks + 2 < 4) {
                load_stage(ks & 1, ks + 2);
                asm volatile("cp.async.wait_group 1;" ::: "memory");
            } else {
                asm volatile("cp.async.wait_group 0;" ::: "memory");
            }
            barg();
            load_frags(0, gbase + ((ks + 1) & 1) * STAGE64G, 0);
        }
    }

    float* red = (float*)sm_raw;
    int rg = lane >> 2, cg = (lane & 3) * 2;
    __syncthreads();
    if (grp == 1) {
#pragma unroll
        for (int mi = 0; mi < 2; mi++)
#pragma unroll
            for (int f = 0; f < 4; f++) {
                int lrr = wm * 32 + mi * 16 + rg;
                int lcc = wn * 32 + (f >> 1) * 16 + (f & 1) * 8 + cg;
#pragma unroll
                for (int half = 0; half < 2; half++) {
                    red[(lrr + half * 8) * 64 + lcc]     = c[mi][f][half * 2];
                    red[(lrr + half * 8) * 64 + lcc + 1] = c[mi][f][half * 2 + 1];
                }
            }
    }
    __syncthreads();
    if (grp == 0) {
        float sc = (MODE == 3 && scaleFlag) ? sqrtf(g_rTr) : 1.f;
#pragma unroll
        for (int mi = 0; mi < 2; mi++)
#pragma unroll
            for (int f = 0; f < 4; f++) {
                int lrr = wm * 32 + mi * 16 + rg;
                int lcc = wn * 32 + (f >> 1) * 16 + (f & 1) * 8 + cg;
#pragma unroll
                for (int half = 0; half < 2; half++) {
                    int r2 = row0 + lrr + half * 8;
                    int cc = col0 + lcc;
                    float v0 = c[mi][f][half * 2]     + red[(lrr + half * 8) * 64 + lcc];
                    float v1 = c[mi][f][half * 2 + 1] + red[(lrr + half * 8) * 64 + lcc + 1];
                    long fi = (long)r2 * C_DIM + cc;
                    if (MODE == 3) {
                        v0 = fmaf(-0.5f, v0, 1.5f * Pf[fi]);
                        v1 = fmaf(-0.5f, v1, 1.5f * Pf[fi + 1]);
                        Pfn[fi] = v0; Pfn[fi + 1] = v1;
                        v0 *= sc; v1 *= sc;
                    }
                    u32 lo, hi = splitpack(v0, v1, lo);
                    ((u32*)outH)[fi >> 1] = hi;
                    ((u32*)outL)[fi >> 1] = lo;
                }
            }
    }
}

__global__ void __launch_bounds__(256, 1) gemm64_pair(
    const bf16* __restrict__ Ph, const bf16* __restrict__ Pl,
    const bf16* __restrict__ Sh, const bf16* __restrict__ Sl)
{
    if (blockIdx.z == 0)
        gemm64_body<2, 0>(Ph, Pl, Ph, Pl, nullptr, nullptr, g_T1h, g_T1l, 0);
    else
        gemm64_body<2, 0>(Ph, Pl, Sh, Sl, nullptr, nullptr, g_Uh, g_Ul, 0);
}

__global__ void __launch_bounds__(256, 1) gemm64_pair_f(
    const bf16* __restrict__ Ph, const bf16* __restrict__ Pl,
    const bf16* __restrict__ Sh, const bf16* __restrict__ Sl)
{
    if (blockIdx.z == 0)
        gemm64_body<2, 1>(Ph, Pl, Ph, Pl, nullptr, nullptr, g_T1h, g_T1l, 0);
    else
        gemm64_body<2, 1>(Ph, Pl, Sh, Sl, nullptr, nullptr, g_Uh, g_Ul, 0);
}

__global__ void __launch_bounds__(256, 1) gemm64_comb(
    const float* __restrict__ Pf, float* __restrict__ Pfn,
    bf16* __restrict__ outH, bf16* __restrict__ outL, int scaleFlag)
{
    gemm64_body<3, 0>(g_T1h, g_T1l, g_Uh, g_Ul, Pf, Pfn, outH, outL, scaleFlag);
}

__global__ void __launch_bounds__(256, 1) gemm64_comb_f(
    const float* __restrict__ Pf, float* __restrict__ Pfn,
    bf16* __restrict__ outH, bf16* __restrict__ outL, int scaleFlag)
{
    gemm64_body<3, 1>(g_T1h, g_T1l, g_Uh, g_Ul, Pf, Pfn, outH, outL, scaleFlag);
}

// ---------------- Sigma_N split (mirrored read) + P1 = 1.5I - 0.5 Sigma_N ----------------
__global__ void finalize_k() {
    int i = blockIdx.x;
    int j2 = threadIdx.x;
    int j = j2 * 2;
    float rtr = 1.0f / (g_tr * INV_M + (float)C_DIM * EPS_V);
    if (i == 0 && j2 == 0) g_rTr = rtr;
    int bi = i >> 7;
    float r0 = (bi <= (j >> 7)) ? g_Gram[(long)i * C_DIM + j] : g_Gram[(long)j * C_DIM + i];
    float r1 = (bi <= ((j + 1) >> 7)) ? g_Gram[(long)i * C_DIM + j + 1] : g_Gram[(long)(j + 1) * C_DIM + i];
    float s0 = r0 * INV_M;
    float s1 = r1 * INV_M;
    if (i == j) s0 += EPS_V;
    if (i == j + 1) s1 += EPS_V;
    s0 *= rtr; s1 *= rtr;
    u32 lo, hi = splitpack(s0, s1, lo);
    ((u32*)g_Sh)[i * 256 + j2] = hi; ((u32*)g_Sl)[i * 256 + j2] = lo;
    float p0 = ((i == j) ? 1.5f : 0.f) - 0.5f * s0;
    float p1 = ((i == j + 1) ? 1.5f : 0.f) - 0.5f * s1;
    g_PfA[(long)i * C_DIM + j] = p0;
    g_PfA[(long)i * C_DIM + j + 1] = p1;
    hi = splitpack(p0, p1, lo);
    ((u32*)g_PAh)[i * 256 + j2] = hi; ((u32*)g_PAl)[i * 256 + j2] = lo;
}

// ---------------- launch ----------------
extern "C" void kernel_launch(void* const* d_in, const int* in_sizes, int n_in,
                              void* d_out, int out_size) {
    const float* X = (const float*)d_in[0];
    float* Out = (float*)d_out;

    cudaFuncSetAttribute(gram_big, cudaFuncAttributeMaxDynamicSharedMemorySize, GSMEM_O);
    cudaFuncSetAttribute(gemm_out, cudaFuncAttributeMaxDynamicSharedMemorySize, GSMEM_O);
    cudaFuncSetAttribute(gemm64_pair, cudaFuncAttributeMaxDynamicSharedMemorySize, NS_SMEM);
    cudaFuncSetAttribute(gemm64_pair_f, cudaFuncAttributeMaxDynamicSharedMemorySize, NS_SMEM);
    cudaFuncSetAttribute(gemm64_comb, cudaFuncAttributeMaxDynamicSharedMemorySize, NS_SMEM);
    cudaFuncSetAttribute(gemm64_comb_f, cudaFuncAttributeMaxDynamicSharedMemorySize, NS_SMEM);

    void *xh, *xl, *xth, *xtl, *sh, *sl, *pah, *pal, *pbh, *pbl;
    void *wh, *wl, *pfa, *pfb, *gram;
    cudaGetSymbolAddress(&xh, g_Xh);   cudaGetSymbolAddress(&xl, g_Xl);
    cudaGetSymbolAddress(&xth, g_Xth); cudaGetSymbolAddress(&xtl, g_Xtl);
    cudaGetSymbolAddress(&sh, g_Sh);   cudaGetSymbolAddress(&sl, g_Sl);
    cudaGetSymbolAddress(&pah, g_PAh); cudaGetSymbolAddress(&pal, g_PAl);
    cudaGetSymbolAddress(&pbh, g_PBh); cudaGetSymbolAddress(&pbl, g_PBl);
    cudaGetSymbolAddress(&wh, g_Wh);   cudaGetSymbolAddress(&wl, g_Wl);
    cudaGetSymbolAddress(&pfa, g_PfA); cudaGetSymbolAddress(&pfb, g_PfB);
    cudaGetSymbolAddress(&gram, g_Gram);

    mean_kernel<<<C_DIM, 256>>>(X);
    conv_fused<<<512, 256>>>(X);

    // Gram = xc xc^T, tri tiles + uneven K split; trace folded into epilogue
    gram_big<<<dim3(6, 1, 29), 256, GSMEM_O>>>(
        (const bf16*)xh, (const bf16*)xl, (float*)gram);

    finalize_k<<<C_DIM, 256>>>();

    // Newton-Schulz iterations 2..5 (iter 1 folded into finalize_k)
    // iters 2,3: FAST hi-only products (errors contract quadratically in iters 4,5)
    float *pfc = (float*)pfa, *pfn = (float*)pfb;
    bf16 *pch = (bf16*)pah, *pcl = (bf16*)pal, *pnh = (bf16*)pbh, *pnl = (bf16*)pbl;
    for (int it = 0; it < 4; it++) {
        int last = (it == 3);
        if (it < 2) {
            gemm64_pair_f<<<dim3(8, 8, 2), 256, NS_SMEM>>>(pch, pcl, (const bf16*)sh, (const bf16*)sl);
            gemm64_comb_f<<<dim3(8, 8), 256, NS_SMEM>>>(
                pfc, pfn, pnh, pnl, 0);
        } else {
            gemm64_pair<<<dim3(8, 8, 2), 256, NS_SMEM>>>(pch, pcl, (const bf16*)sh, (const bf16*)sl);
            gemm64_comb<<<dim3(8, 8), 256, NS_SMEM>>>(
                pfc, pfn, last ? (bf16*)wh : pnh, last ? (bf16*)wl : pnl, last);
        }
        float* tf = pfc; pfc = pfn; pfn = tf;
        bf16* th = pch; pch = pnh; pnh = th;
        bf16* tl = pcl; pcl = pnl; pnl = tl;
    }

    // Out[c][m] = W @ xc, written NCHW; grid x = row tiles (B shared via L2)
    gemm_out<<<dim3(4, 256), 256, GSMEM_O>>>(
        (const bf16*)wh, (const bf16*)wl,
        (const bf16*)xth, (const bf16*)xtl, Out);
}

// round 17
// speedup vs baseline: 1.0555x; 1.0139x over previous
#include <cuda_runtime.h>
#include <cuda_bf16.h>
#include <stdint.h>
#include <math.h>

typedef __nv_bfloat16 bf16;
typedef unsigned int u32;

#define C_DIM 512
#define M_TOT 65536
#define INV_M (1.0f / 65536.0f)
#define EPS_V 1e-5f

#define ROWB 144                 // 64 bf16 = 128B data + 16B pad
// 128x256 tiling (gram_big + gemm_out): BK=64, 8 warps (2x4), warp 64x64
#define TILE_A (128 * ROWB)      // 18432
#define TILE_BO (256 * ROWB)     // 36864
#define OFF_B (2 * TILE_A)       // 36864
#define STAGE_O (2 * TILE_A + 2 * TILE_BO)  // 110592
#define GSMEM_O (2 * STAGE_O)    // 221184

// NS tiling: CTA 64x64, 256 threads, 2 K-groups of 4 warps
#define TILE64 (64 * ROWB)       // 9216
#define STAGE64G (4 * TILE64)    // 36864
#define NS_SMEM (4 * STAGE64G)   // 147456

// gram tri tiling: 4 wide (128x256) + 2 narrow (128x128) tiles
__constant__ int c_tr[6] = {0, 0, 128, 256, 128, 384};
__constant__ int c_tc[6] = {0, 256, 256, 256, 128, 384};

// ---------------- scratch ----------------
__device__ float g_mean[C_DIM];
__device__ float g_Gram[C_DIM * C_DIM];
__device__ float g_rTr;
__device__ float g_tr;
__device__ bf16 g_Xh[33554432];   // centered X, [c][m]
__device__ bf16 g_Xl[33554432];
__device__ bf16 g_Xth[33554432];  // centered X, [m][c]
__device__ bf16 g_Xtl[33554432];
__device__ bf16 g_Sh[C_DIM * C_DIM], g_Sl[C_DIM * C_DIM];
__device__ bf16 g_PAh[C_DIM * C_DIM], g_PAl[C_DIM * C_DIM];
__device__ bf16 g_PBh[C_DIM * C_DIM], g_PBl[C_DIM * C_DIM];
__device__ bf16 g_T1h[C_DIM * C_DIM], g_T1l[C_DIM * C_DIM];
__device__ bf16 g_Uh[C_DIM * C_DIM], g_Ul[C_DIM * C_DIM];
__device__ bf16 g_Wh[C_DIM * C_DIM], g_Wl[C_DIM * C_DIM];
__device__ float g_PfA[C_DIM * C_DIM], g_PfB[C_DIM * C_DIM];

// ---------------- helpers ----------------
__device__ __forceinline__ u32 s2u(const void* p) {
    u32 a;
    asm("{ .reg .u64 t; cvta.to.shared.u64 t, %1; cvt.u32.u64 %0, t; }" : "=r"(a) : "l"(p));
    return a;
}
__device__ __forceinline__ void cpasync16(u32 dst, const void* src) {
    asm volatile("cp.async.cg.shared.global [%0], [%1], 16;" :: "r"(dst), "l"(src));
}
__device__ __forceinline__ void ldm4(u32* r, u32 addr) {
    asm volatile("ldmatrix.sync.aligned.m8n8.x4.shared.b16 {%0,%1,%2,%3}, [%4];"
                 : "=r"(r[0]), "=r"(r[1]), "=r"(r[2]), "=r"(r[3]) : "r"(addr));
}
__device__ __forceinline__ void mma16816(float* c, const u32* a, u32 b0, u32 b1) {
    asm volatile("mma.sync.aligned.m16n8k16.row.col.f32.bf16.bf16.f32 "
                 "{%0,%1,%2,%3}, {%4,%5,%6,%7}, {%8,%9}, {%0,%1,%2,%3};"
                 : "+f"(c[0]), "+f"(c[1]), "+f"(c[2]), "+f"(c[3])
                 : "r"(a[0]), "r"(a[1]), "r"(a[2]), "r"(a[3]), "r"(b0), "r"(b1));
}
__device__ __forceinline__ u32 splitpack(float a, float b, u32& lop) {
    bf16 h0 = __float2bfloat16(a), h1 = __float2bfloat16(b);
    bf16 l0 = __float2bfloat16(a - __bfloat162float(h0));
    bf16 l1 = __float2bfloat16(b - __bfloat162float(h1));
    __nv_bfloat162 hv, lv;
    hv.x = h0; hv.y = h1; lv.x = l0; lv.y = l1;
    lop = *(u32*)&lv;
    return *(u32*)&hv;
}

// ---------------- mean per channel + zero Gram + zero trace ----------------
__global__ void mean_kernel(const float* __restrict__ X) {
    int c = blockIdx.x;
    float s = 0.f;
    for (int idx = threadIdx.x; idx < (M_TOT / 4); idx += 256) {
        int n = idx >> 8, h4 = idx & 255;
        const float4 v = *(const float4*)&X[(((size_t)(n * C_DIM + c)) << 10) + (size_t)h4 * 4];
        s += (v.x + v.y) + (v.z + v.w);
    }
    __shared__ float red[256];
    red[threadIdx.x] = s;
    __syncthreads();
    for (int off = 128; off > 0; off >>= 1) {
        if (threadIdx.x < off) red[threadIdx.x] += red[threadIdx.x + off];
        __syncthreads();
    }
    if (threadIdx.x == 0) g_mean[c] = red[0] * INV_M;
    for (int j = threadIdx.x; j < C_DIM; j += 256) g_Gram[(long)c * C_DIM + j] = 0.f;
    if (c == 0 && threadIdx.x == 0) g_tr = 0.f;
}

// ---------------- fused center+split: X -> [c][m] AND [m][c] layouts ----------------
__global__ void conv_fused(const float* __restrict__ X) {
    __shared__ float smf[64][129];
    int b = blockIdx.x;
    int n = b >> 3, hw0 = (b & 7) << 7;
    int tid = threadIdx.x;
    for (int cb = 0; cb < 8; cb++) {
        __syncthreads();
        for (int l = tid; l < 64 * 32; l += 256) {
            int cl = l >> 5, f4 = (l & 31) * 4;
            int ch = cb * 64 + cl;
            float4 v = *(const float4*)&X[(((long)(n * C_DIM + ch)) << 10) + hw0 + f4];
            float mu = g_mean[ch];
            smf[cl][f4] = v.x - mu; smf[cl][f4 + 1] = v.y - mu;
            smf[cl][f4 + 2] = v.z - mu; smf[cl][f4 + 3] = v.w - mu;
        }
        __syncthreads();
        for (int l = tid; l < 128 * 32; l += 256) {
            int r = l >> 5, j = l & 31;
            u32 lo, hi = splitpack(smf[2 * j][r], smf[2 * j + 1][r], lo);
            long m = (long)n * 1024 + hw0 + r;
            ((u32*)&g_Xth[m * C_DIM])[cb * 32 + j] = hi;
            ((u32*)&g_Xtl[m * C_DIM])[cb * 32 + j] = lo;
        }
        for (int l = tid; l < 64 * 64; l += 256) {
            int cl = l >> 6, p = l & 63;
            u32 lo, hi = splitpack(smf[cl][2 * p], smf[cl][2 * p + 1], lo);
            long c = cb * 64 + cl;
            long u = (c << 15) + ((n * 1024 + hw0) >> 1) + p;
            ((u32*)g_Xh)[u] = hi;
            ((u32*)g_Xl)[u] = lo;
        }
    }
}

// ---------------- gram: tri tiles, warp 64x64/64x32, trace folded into epilogue ----------------
__global__ void __launch_bounds__(256, 1) gram_big(
    const bf16* __restrict__ Ah, const bf16* __restrict__ Al,
    float* __restrict__ outF)
{
    extern __shared__ char sm_raw[];
    u32 sbase = s2u(sm_raw);
    int tid = threadIdx.x, lane = tid & 31, wid = tid >> 5;
    int wm = wid >> 2, wn = wid & 3;
    int t = blockIdx.x;
    bool wide = t < 4;
    const int row0 = c_tr[t], col0 = c_tc[t];
    int z = blockIdx.z;
    int nSteps, s0;
    if (wide) { nSteps = 35 + (z < 9 ? 1 : 0); s0 = z * 35 + (z < 9 ? z : 9); }
    else {
        if (z >= 15) return;
        nSteps = 68 + (z < 4 ? 1 : 0); s0 = z * 68 + (z < 4 ? z : 4);
    }
    long k0 = (long)s0 << 6;

    float c[4][8][4];
#pragma unroll
    for (int mi = 0; mi < 4; mi++)
#pragma unroll
        for (int f = 0; f < 8; f++)
#pragma unroll
            for (int q = 0; q < 4; q++) c[mi][f][q] = 0.f;

    u32 ah[4][4], al[4][4];

    auto load_stage = [&](int st, int ks) {
        u32 sb = sbase + st * STAGE_O;
        long kg = k0 + ((long)ks << 6);
#pragma unroll
        for (int tt = 0; tt < 2; tt++) {
            const bf16* g = tt ? Al : Ah;
#pragma unroll
            for (int rep = 0; rep < 4; rep++) {
                int idx = tid + rep * 256;
                int r = idx >> 3, ch = idx & 7;
                cpasync16(sb + tt * TILE_A + r * ROWB + ch * 16,
                          g + (long)(row0 + r) * M_TOT + kg + ch * 8);
            }
        }
        if (wide) {
#pragma unroll
            for (int tt = 0; tt < 2; tt++) {
                const bf16* g = tt ? Al : Ah;
#pragma unroll
                for (int rep = 0; rep < 8; rep++) {
                    int idx = tid + rep * 256;
                    int r = idx >> 3, ch = idx & 7;
                    cpasync16(sb + OFF_B + tt * TILE_BO + r * ROWB + ch * 16,
                              g + (long)(col0 + r) * M_TOT + kg + ch * 8);
                }
            }
        } else {
#pragma unroll
            for (int tt = 0; tt < 2; tt++) {
                const bf16* g = tt ? Al : Ah;
#pragma unroll
                for (int rep = 0; rep < 4; rep++) {
                    int idx = tid + rep * 256;
                    int r = idx >> 3, ch = idx & 7;
                    cpasync16(sb + OFF_B + tt * TILE_BO + r * ROWB + ch * 16,
                              g + (long)(col0 + r) * M_TOT + kg + ch * 8);
                }
            }
        }
        asm volatile("cp.async.commit_group;");
    };

    load_stage(0, 0);
    load_stage(1, 1);
    asm volatile("cp.async.wait_group 1;" ::: "memory");
    __syncthreads();

    for (int ks = 0; ks < nSteps; ks++) {
        u32 sb = sbase + (ks & 1) * STAGE_O;
#pragma unroll
        for (int kk = 0; kk < 4; kk++) {
            int kcol = kk * 16;
#pragma unroll
            for (int mi = 0; mi < 4; mi++) {
                int r = wm * 64 + mi * 16 + (lane & 15);
                int cb = (kcol + (lane >> 4) * 8) * 2;
                ldm4(ah[mi], sb + 0 * TILE_A + r * ROWB + cb);
                ldm4(al[mi], sb + 1 * TILE_A + r * ROWB + cb);
            }
            if (wide) {
#pragma unroll
                for (int bq = 0; bq < 4; bq++) {
                    u32 bh4[4], bl4[4];
                    int r = wn * 64 + bq * 16 + (lane & 7) + ((lane >> 4) << 3);
                    int cb = (kcol + ((lane >> 3) & 1) * 8) * 2;
                    ldm4(bh4, sb + OFF_B + 0 * TILE_BO + r * ROWB + cb);
                    ldm4(bl4, sb + OFF_B + 1 * TILE_BO + r * ROWB + cb);
#pragma unroll
                    for (int mi = 0; mi < 4; mi++) {
                        mma16816(c[mi][bq * 2],     ah[mi], bh4[0], bh4[1]);
                        mma16816(c[mi][bq * 2 + 1], ah[mi], bh4[2], bh4[3]);
                        mma16816(c[mi][bq * 2],     ah[mi], bl4[0], bl4[1]);
                        mma16816(c[mi][bq * 2 + 1], ah[mi], bl4[2], bl4[3]);
                        mma16816(c[mi][bq * 2],     al[mi], bh4[0], bh4[1]);
                        mma16816(c[mi][bq * 2 + 1], al[mi], bh4[2], bh4[3]);
                    }
                }
            } else {
#pragma unroll
                for (int bq = 0; bq < 2; bq++) {
                    u32 bh4[4], bl4[4];
                    int r = wn * 32 + bq * 16 + (lane & 7) + ((lane >> 4) << 3);
                    int cb = (kcol + ((lane >> 3) & 1) * 8) * 2;
                    ldm4(bh4, sb + OFF_B + 0 * TILE_BO + r * ROWB + cb);
                    ldm4(bl4, sb + OFF_B + 1 * TILE_BO + r * ROWB + cb);
#pragma unroll
                    for (int mi = 0; mi < 4; mi++) {
                        mma16816(c[mi][bq * 2],     ah[mi], bh4[0], bh4[1]);
                        mma16816(c[mi][bq * 2 + 1], ah[mi], bh4[2], bh4[3]);
                        mma16816(c[mi][bq * 2],     ah[mi], bl4[0], bl4[1]);
                        mma16816(c[mi][bq * 2 + 1], ah[mi], bl4[2], bl4[3]);
                        mma16816(c[mi][bq * 2],     al[mi], bh4[0], bh4[1]);
                        mma16816(c[mi][bq * 2 + 1], al[mi], bh4[2], bh4[3]);
                    }
                }
            }
        }
        if (ks + 1 < nSteps) {
            __syncthreads();
            if (ks + 2 < nSteps) {
                load_stage(ks & 1, ks + 2);
                asm volatile("cp.async.wait_group 1;" ::: "memory");
            } else {
                asm volatile("cp.async.wait_group 0;" ::: "memory");
            }
            __syncthreads();
        }
    }

    int rg = lane >> 2, cg = (lane & 3) * 2;
    int nf = wide ? 8 : 4;
    int wstride = wide ? 64 : 32;
#pragma unroll
    for (int mi = 0; mi < 4; mi++)
        for (int f = 0; f < nf; f++) {
            int rr = row0 + wm * 64 + mi * 16 + rg;
            int cc = col0 + wn * wstride + f * 8 + cg;
            atomicAdd(&outF[(long)rr * C_DIM + cc],           c[mi][f][0]);
            atomicAdd(&outF[(long)rr * C_DIM + cc + 1],       c[mi][f][1]);
            atomicAdd(&outF[(long)(rr + 8) * C_DIM + cc],     c[mi][f][2]);
            atomicAdd(&outF[(long)(rr + 8) * C_DIM + cc + 1], c[mi][f][3]);
            if (rr == cc)         atomicAdd(&g_tr, c[mi][f][0]);
            if (rr == cc + 1)     atomicAdd(&g_tr, c[mi][f][1]);
            if (rr + 8 == cc)     atomicAdd(&g_tr, c[mi][f][2]);
            if (rr + 8 == cc + 1) atomicAdd(&g_tr, c[mi][f][3]);
        }
}

// ---------------- out GEMM: CTA 128x256, BK=64, 2-stage, L2-friendly grid, NCHW epilogue ----------------
__global__ void __launch_bounds__(256, 1) gemm_out(
    const bf16* __restrict__ Ah, const bf16* __restrict__ Al,
    const bf16* __restrict__ Bh, const bf16* __restrict__ Bl,
    float* __restrict__ outF)
{
    extern __shared__ char sm_raw[];
    u32 sbase = s2u(sm_raw);
    int tid = threadIdx.x, lane = tid & 31, wid = tid >> 5;
    int wm = wid >> 2, wn = wid & 3;
    const int row0 = blockIdx.x * 128;   // 4 adjacent CTAs share B col-tile in L2
    const int col0 = blockIdx.y * 256;
    const int nSteps = 8;

    float c[4][8][4];
#pragma unroll
    for (int mi = 0; mi < 4; mi++)
#pragma unroll
        for (int f = 0; f < 8; f++)
#pragma unroll
            for (int q = 0; q < 4; q++) c[mi][f][q] = 0.f;

    u32 ah[4][4], al[4][4];

    auto load_stage = [&](int st, int ks) {
        u32 sb = sbase + st * STAGE_O;
        long kg = (long)ks << 6;
#pragma unroll
        for (int t = 0; t < 2; t++) {
            const bf16* g = t ? Al : Ah;
#pragma unroll
            for (int rep = 0; rep < 4; rep++) {
                int idx = tid + rep * 256;
                int r = idx >> 3, ch = idx & 7;
                cpasync16(sb + t * TILE_A + r * ROWB + ch * 16,
                          g + (long)(row0 + r) * C_DIM + kg + ch * 8);
            }
        }
#pragma unroll
        for (int t = 0; t < 2; t++) {
            const bf16* g = t ? Bl : Bh;
#pragma unroll
            for (int rep = 0; rep < 8; rep++) {
                int idx = tid + rep * 256;
                int r = idx >> 3, ch = idx & 7;
                cpasync16(sb + OFF_B + t * TILE_BO + r * ROWB + ch * 16,
                          g + (long)(col0 + r) * C_DIM + kg + ch * 8);
            }
        }
        asm volatile("cp.async.commit_group;");
    };

    load_stage(0, 0);
    load_stage(1, 1);
    asm volatile("cp.async.wait_group 1;" ::: "memory");
    __syncthreads();

    for (int ks = 0; ks < nSteps; ks++) {
        u32 sb = sbase + (ks & 1) * STAGE_O;
#pragma unroll
        for (int kk = 0; kk < 4; kk++) {
            int kcol = kk * 16;
#pragma unroll
            for (int mi = 0; mi < 4; mi++) {
                int r = wm * 64 + mi * 16 + (lane & 15);
                int cb = (kcol + (lane >> 4) * 8) * 2;
                ldm4(ah[mi], sb + 0 * TILE_A + r * ROWB + cb);
                ldm4(al[mi], sb + 1 * TILE_A + r * ROWB + cb);
            }
#pragma unroll
            for (int bq = 0; bq < 4; bq++) {
                u32 bh4[4], bl4[4];
                int r = wn * 64 + bq * 16 + (lane & 7) + ((lane >> 4) << 3);
                int cb = (kcol + ((lane >> 3) & 1) * 8) * 2;
                ldm4(bh4, sb + OFF_B + 0 * TILE_BO + r * ROWB + cb);
                ldm4(bl4, sb + OFF_B + 1 * TILE_BO + r * ROWB + cb);
#pragma unroll
                for (int mi = 0; mi < 4; mi++) {
                    mma16816(c[mi][bq * 2],     ah[mi], bh4[0], bh4[1]);
                    mma16816(c[mi][bq * 2 + 1], ah[mi], bh4[2], bh4[3]);
                    mma16816(c[mi][bq * 2],     ah[mi], bl4[0], bl4[1]);
                    mma16816(c[mi][bq * 2 + 1], ah[mi], bl4[2], bl4[3]);
                    mma16816(c[mi][bq * 2],     al[mi], bh4[0], bh4[1]);
                    mma16816(c[mi][bq * 2 + 1], al[mi], bh4[2], bh4[3]);
                }
            }
        }
        if (ks + 1 < nSteps) {
            __syncthreads();
            if (ks + 2 < nSteps) {
                load_stage(ks & 1, ks + 2);
                asm volatile("cp.async.wait_group 1;" ::: "memory");
            } else {
                asm volatile("cp.async.wait_group 0;" ::: "memory");
            }
            __syncthreads();
        }
    }

    __syncthreads();
    float* st = (float*)sm_raw;
    const int LDS = 260;
    int rg = lane >> 2, cg = (lane & 3) * 2;
#pragma unroll
    for (int mi = 0; mi < 4; mi++)
#pragma unroll
        for (int f = 0; f < 8; f++) {
            int rr = wm * 64 + mi * 16 + rg;
            int cc = wn * 64 + f * 8 + cg;
            st[rr * LDS + cc] = c[mi][f][0];
            st[rr * LDS + cc + 1] = c[mi][f][1];
            st[(rr + 8) * LDS + cc] = c[mi][f][2];
            st[(rr + 8) * LDS + cc + 1] = c[mi][f][3];
        }
    __syncthreads();
    int n = col0 >> 10, hw0 = col0 & 1023;
    for (int l = tid; l < 128 * 64; l += 256) {
        int r = l >> 6, q = l & 63;
        float4 v = *(float4*)&st[r * LDS + q * 4];
        *(float4*)&outF[(((long)(n * C_DIM + row0 + r)) << 10) + hw0 + q * 4] = v;
    }
}

// ---------------- NS GEMM core: 64x64 tile, 256 thr, 2 K-groups; FAST = hi-only products ----------------
template<int MODE, int FAST>   // MODE 2: split write ; 3: NS combine
__device__ __forceinline__ void gemm64_body(
    const bf16* Ah, const bf16* Al, const bf16* Bh, const bf16* Bl,
    const float* Pf, float* Pfn, bf16* outH, bf16* outL, int scaleFlag)
{
    extern __shared__ char sm_raw[];
    u32 sbase = s2u(sm_raw);
    int tid = threadIdx.x, lane = tid & 31, wid = tid >> 5;
    int grp = wid >> 2, wi = wid & 3;
    int wm = wi >> 1, wn = wi & 1;
    int tg = tid & 127;
    const int row0 = blockIdx.y * 64, col0 = blockIdx.x * 64;
    u32 gbase = sbase + grp * (2 * STAGE64G);

    auto barg = [&]() {
        asm volatile("bar.sync %0, %1;" :: "r"(grp + 1), "r"(128) : "memory");
    };

    float c[2][4][4];
#pragma unroll
    for (int mi = 0; mi < 2; mi++)
#pragma unroll
        for (int f = 0; f < 4; f++)
#pragma unroll
            for (int q = 0; q < 4; q++) c[mi][f][q] = 0.f;

    u32 ah[2][2][4], al[2][2][4], bh[2][2][4], bl[2][2][4];

    auto load_stage = [&](int st, int ks) {
        u32 sb = gbase + st * STAGE64G;
        long kg = (long)grp * 256 + ((long)ks << 6);
#pragma unroll
        for (int t = 0; t < 4; t++) {
            if (FAST && (t == 1 || t == 3)) continue;
            const bf16* g = (t == 0) ? Ah : (t == 1) ? Al : (t == 2) ? Bh : Bl;
            long rbase = (t < 2) ? row0 : col0;
#pragma unroll
            for (int rep = 0; rep < 4; rep++) {
                int idx = tg + rep * 128;
                int r = idx >> 3, ch = idx & 7;
                cpasync16(sb + t * TILE64 + r * ROWB + ch * 16,
                          g + (rbase + r) * C_DIM + kg + ch * 8);
            }
        }
        asm volatile("cp.async.commit_group;");
    };
    auto load_frags = [&](int fb, u32 sb, int kk) {
        int kcol = kk * 16;
#pragma unroll
        for (int mi = 0; mi < 2; mi++) {
            int r = wm * 32 + mi * 16 + (lane & 15);
            int cb = (kcol + (lane >> 4) * 8) * 2;
            ldm4(ah[fb][mi], sb + 0 * TILE64 + r * ROWB + cb);
            if (!FAST) ldm4(al[fb][mi], sb + 1 * TILE64 + r * ROWB + cb);
        }
#pragma unroll
        for (int nj = 0; nj < 2; nj++) {
            int r = wn * 32 + nj * 16 + (lane & 7) + ((lane >> 4) << 3);
            int cb = (kcol + ((lane >> 3) & 1) * 8) * 2;
            ldm4(bh[fb][nj], sb + 2 * TILE64 + r * ROWB + cb);
            if (!FAST) ldm4(bl[fb][nj], sb + 3 * TILE64 + r * ROWB + cb);
        }
    };
    auto mma_all = [&](int fb) {
#pragma unroll
        for (int mi = 0; mi < 2; mi++)
#pragma unroll
            for (int nj = 0; nj < 2; nj++) {
                mma16816(c[mi][nj * 2],     ah[fb][mi], bh[fb][nj][0], bh[fb][nj][1]);
                mma16816(c[mi][nj * 2 + 1], ah[fb][mi], bh[fb][nj][2], bh[fb][nj][3]);
                if (!FAST) {
                    mma16816(c[mi][nj * 2],     ah[fb][mi], bl[fb][nj][0], bl[fb][nj][1]);
                    mma16816(c[mi][nj * 2 + 1], ah[fb][mi], bl[fb][nj][2], bl[fb][nj][3]);
                    mma16816(c[mi][nj * 2],     al[fb][mi], bh[fb][nj][0], bh[fb][nj][1]);
                    mma16816(c[mi][nj * 2 + 1], al[fb][mi], bh[fb][nj][2], bh[fb][nj][3]);
                }
            }
    };

    load_stage(0, 0);
    load_stage(1, 1);
    asm volatile("cp.async.wait_group 1;" ::: "memory");
    barg();
    load_frags(0, gbase, 0);

    for (int ks = 0; ks < 4; ks++) {
        u32 sb = gbase + (ks & 1) * STAGE64G;
#pragma unroll
        for (int kk = 0; kk < 4; kk++) {
            if (kk < 3) load_frags((kk + 1) & 1, sb, kk + 1);
            mma_all(kk & 1);
        }
        if (ks + 1 < 4) {
            barg();
            if (ks + 2 < 4) {
                load_stage(ks & 1, ks + 2);
                asm volatile("cp.async.wait_group 1;" ::: "memory");
            } else {
                asm volatile("cp.async.wait_group 0;" ::: "memory");
            }
            barg();
            load_frags(0, gbase + ((ks + 1) & 1) * STAGE64G, 0);
        }
    }

    float* red = (float*)sm_raw;
    int rg = lane >> 2, cg = (lane & 3) * 2;
    __syncthreads();
    if (grp == 1) {
#pragma unroll
        for (int mi = 0; mi < 2; mi++)
#pragma unroll
            for (int f = 0; f < 4; f++) {
                int lrr = wm * 32 + mi * 16 + rg;
                int lcc = wn * 32 + (f >> 1) * 16 + (f & 1) * 8 + cg;
#pragma unroll
                for (int half = 0; half < 2; half++) {
                    red[(lrr + half * 8) * 64 + lcc]     = c[mi][f][half * 2];
                    red[(lrr + half * 8) * 64 + lcc + 1] = c[mi][f][half * 2 + 1];
                }
            }
    }
    __syncthreads();
    if (grp == 0) {
        float sc = (MODE == 3 && scaleFlag) ? sqrtf(g_rTr) : 1.f;
#pragma unroll
        for (int mi = 0; mi < 2; mi++)
#pragma unroll
            for (int f = 0; f < 4; f++) {
                int lrr = wm * 32 + mi * 16 + rg;
                int lcc = wn * 32 + (f >> 1) * 16 + (f & 1) * 8 + cg;
#pragma unroll
                for (int half = 0; half < 2; half++) {
                    int r2 = row0 + lrr + half * 8;
                    int cc = col0 + lcc;
                    float v0 = c[mi][f][half * 2]     + red[(lrr + half * 8) * 64 + lcc];
                    float v1 = c[mi][f][half * 2 + 1] + red[(lrr + half * 8) * 64 + lcc + 1];
                    long fi = (long)r2 * C_DIM + cc;
                    if (MODE == 3) {
                        v0 = fmaf(-0.5f, v0, 1.5f * Pf[fi]);
                        v1 = fmaf(-0.5f, v1, 1.5f * Pf[fi + 1]);
                        Pfn[fi] = v0; Pfn[fi + 1] = v1;
                        v0 *= sc; v1 *= sc;
                    }
                    u32 lo, hi = splitpack(v0, v1, lo);
                    ((u32*)outH)[fi >> 1] = hi;
                    ((u32*)outL)[fi >> 1] = lo;
                }
            }
    }
}

__global__ void __launch_bounds__(256, 1) gemm64_pair(
    const bf16* __restrict__ Ph, const bf16* __restrict__ Pl,
    const bf16* __restrict__ Sh, const bf16* __restrict__ Sl)
{
    if (blockIdx.z == 0)
        gemm64_body<2, 0>(Ph, Pl, Ph, Pl, nullptr, nullptr, g_T1h, g_T1l, 0);
    else
        gemm64_body<2, 0>(Ph, Pl, Sh, Sl, nullptr, nullptr, g_Uh, g_Ul, 0);
}

__global__ void __launch_bounds__(256, 1) gemm64_pair_f(
    const bf16* __restrict__ Ph, const bf16* __restrict__ Pl,
    const bf16* __restrict__ Sh, const bf16* __restrict__ Sl)
{
    if (blockIdx.z == 0)
        gemm64_body<2, 1>(Ph, Pl, Ph, Pl, nullptr, nullptr, g_T1h, g_T1l, 0);
    else
        gemm64_body<2, 1>(Ph, Pl, Sh, Sl, nullptr, nullptr, g_Uh, g_Ul, 0);
}

__global__ void __launch_bounds__(256, 1) gemm64_comb(
    const float* __restrict__ Pf, float* __restrict__ Pfn,
    bf16* __restrict__ outH, bf16* __restrict__ outL, int scaleFlag)
{
    gemm64_body<3, 0>(g_T1h, g_T1l, g_Uh, g_Ul, Pf, Pfn, outH, outL, scaleFlag);
}

__global__ void __launch_bounds__(256, 1) gemm64_comb_f(
    const float* __restrict__ Pf, float* __restrict__ Pfn,
    bf16* __restrict__ outH, bf16* __restrict__ outL, int scaleFlag)
{
    gemm64_body<3, 1>(g_T1h, g_T1l, g_Uh, g_Ul, Pf, Pfn, outH, outL, scaleFlag);
}

// ---------------- Sigma_N split (mirrored read) + P1 = 1.5I - 0.5 Sigma_N ----------------
__global__ void finalize_k() {
    int i = blockIdx.x;
    int j2 = threadIdx.x;
    int j = j2 * 2;
    float rtr = 1.0f / (g_tr * INV_M + (float)C_DIM * EPS_V);
    if (i == 0 && j2 == 0) g_rTr = rtr;
    int bi = i >> 7;
    float r0 = (bi <= (j >> 7)) ? g_Gram[(long)i * C_DIM + j] : g_Gram[(long)j * C_DIM + i];
    float r1 = (bi <= ((j + 1) >> 7)) ? g_Gram[(long)i * C_DIM + j + 1] : g_Gram[(long)(j + 1) * C_DIM + i];
    float s0 = r0 * INV_M;
    float s1 = r1 * INV_M;
    if (i == j) s0 += EPS_V;
    if (i == j + 1) s1 += EPS_V;
    s0 *= rtr; s1 *= rtr;
    u32 lo, hi = splitpack(s0, s1, lo);
    ((u32*)g_Sh)[i * 256 + j2] = hi; ((u32*)g_Sl)[i * 256 + j2] = lo;
    float p0 = ((i == j) ? 1.5f : 0.f) - 0.5f * s0;
    float p1 = ((i == j + 1) ? 1.5f : 0.f) - 0.5f * s1;
    g_PfA[(long)i * C_DIM + j] = p0;
    g_PfA[(long)i * C_DIM + j + 1] = p1;
    hi = splitpack(p0, p1, lo);
    ((u32*)g_PAh)[i * 256 + j2] = hi; ((u32*)g_PAl)[i * 256 + j2] = lo;
}

// ---------------- launch ----------------
extern "C" void kernel_launch(void* const* d_in, const int* in_sizes, int n_in,
                              void* d_out, int out_size) {
    const float* X = (const float*)d_in[0];
    float* Out = (float*)d_out;

    cudaFuncSetAttribute(gram_big, cudaFuncAttributeMaxDynamicSharedMemorySize, GSMEM_O);
    cudaFuncSetAttribute(gemm_out, cudaFuncAttributeMaxDynamicSharedMemorySize, GSMEM_O);
    cudaFuncSetAttribute(gemm64_pair, cudaFuncAttributeMaxDynamicSharedMemorySize, NS_SMEM);
    cudaFuncSetAttribute(gemm64_pair_f, cudaFuncAttributeMaxDynamicSharedMemorySize, NS_SMEM);
    cudaFuncSetAttribute(gemm64_comb, cudaFuncAttributeMaxDynamicSharedMemorySize, NS_SMEM);
    cudaFuncSetAttribute(gemm64_comb_f, cudaFuncAttributeMaxDynamicSharedMemorySize, NS_SMEM);

    void *xh, *xl, *xth, *xtl, *sh, *sl, *pah, *pal, *pbh, *pbl;
    void *wh, *wl, *pfa, *pfb, *gram;
    cudaGetSymbolAddress(&xh, g_Xh);   cudaGetSymbolAddress(&xl, g_Xl);
    cudaGetSymbolAddress(&xth, g_Xth); cudaGetSymbolAddress(&xtl, g_Xtl);
    cudaGetSymbolAddress(&sh, g_Sh);   cudaGetSymbolAddress(&sl, g_Sl);
    cudaGetSymbolAddress(&pah, g_PAh); cudaGetSymbolAddress(&pal, g_PAl);
    cudaGetSymbolAddress(&pbh, g_PBh); cudaGetSymbolAddress(&pbl, g_PBl);
    cudaGetSymbolAddress(&wh, g_Wh);   cudaGetSymbolAddress(&wl, g_Wl);
    cudaGetSymbolAddress(&pfa, g_PfA); cudaGetSymbolAddress(&pfb, g_PfB);
    cudaGetSymbolAddress(&gram, g_Gram);

    mean_kernel<<<C_DIM, 256>>>(X);
    conv_fused<<<512, 256>>>(X);

    // Gram = xc xc^T, tri tiles + uneven K split; trace folded into epilogue
    gram_big<<<dim3(6, 1, 29), 256, GSMEM_O>>>(
        (const bf16*)xh, (const bf16*)xl, (float*)gram);

    finalize_k<<<C_DIM, 256>>>();

    // Newton-Schulz iterations 2..5 (iter 1 folded into finalize_k)
    // iters 2,3,4: FAST hi-only products; only iter 5 full bf16x3
    float *pfc = (float*)pfa, *pfn = (float*)pfb;
    bf16 *pch = (bf16*)pah, *pcl = (bf16*)pal, *pnh = (bf16*)pbh, *pnl = (bf16*)pbl;
    for (int it = 0; it < 4; it++) {
        int last = (it == 3);
        if (it < 3) {
            gemm64_pair_f<<<dim3(8, 8, 2), 256, NS_SMEM>>>(pch, pcl, (const bf16*)sh, (const bf16*)sl);
            gemm64_comb_f<<<dim3(8, 8), 256, NS_SMEM>>>(
                pfc, pfn, pnh, pnl, 0);
        } else {
            gemm64_pair<<<dim3(8, 8, 2), 256, NS_SMEM>>>(pch, pcl, (const bf16*)sh, (const bf16*)sl);
            gemm64_comb<<<dim3(8, 8), 256, NS_SMEM>>>(
                pfc, pfn, last ? (bf16*)wh : pnh, last ? (bf16*)wl : pnl, last);
        }
        float* tf = pfc; pfc = pfn; pfn = tf;
        bf16* th = pch; pch = pnh; pnh = th;
        bf16* tl = pcl; pcl = pnl; pnl = tl;
    }

    // Out[c][m] = W @ xc, written NCHW; grid x = row tiles (B shared via L2)
    gemm_out<<<dim3(4, 256), 256, GSMEM_O>>>(
        (const bf16*)wh, (const bf16*)wl,
        (const bf16*)xth, (const bf16*)xtl, Out);
}